// round 1
// baseline (speedup 1.0000x reference)
#include <cuda_runtime.h>
#include <cstdint>
#include <cstdio>

// Problem constants (fixed shapes for this problem instance)
#define MAX_NODES 100000
#define HIDF 128
#define OUTF 64

// ---------------- device scratch (static allocation; no cudaMalloc allowed) ----
__device__ __align__(128) float g_h   [(size_t)MAX_NODES * HIDF]; // x@W1
__device__ __align__(128) float g_acc1[(size_t)MAX_NODES * HIDF]; // gcn1 accumulator
__device__ __align__(128) float g_g   [(size_t)MAX_NODES * OUTF]; // h2@W2
__device__ __align__(128) float g_acc2[(size_t)MAX_NODES * OUTF]; // gcn2 accumulator
__device__ __align__(128) float g_deg [MAX_NODES];
__device__ __align__(128) float g_dinv[MAX_NODES];

// ---------------- degree ------------------------------------------------------
__global__ void deg_kernel(const int* __restrict__ dst, int E, float* __restrict__ deg) {
    int i = blockIdx.x * blockDim.x + threadIdx.x;
    if (i < E) atomicAdd(&deg[dst[i]], 1.0f);
}

__global__ void dinv_kernel(const float* __restrict__ deg, float* __restrict__ dinv, int n) {
    int i = blockIdx.x * blockDim.x + threadIdx.x;
    if (i < n) dinv[i] = rsqrtf(deg[i] + 1.0f);  // +1 self loop
}

// ---------------- tiled SGEMM -------------------------------------------------
// C_raw[row,col]    = sum_k f(A[row,k]) * B[k,col]
// C_scaled[row,col] = dinv[row]^2 * C_raw[row,col]     (self-loop init for scatter)
// MODE 0: f = identity.  MODE 1: f(a) = 0.9*max(a + bias[k], 0) + 0.1  (relu+CRF mix)
template<int BM, int BN, int BK, int TM, int TN, int MODE>
__global__ __launch_bounds__((BM/TM)*(BN/TN))
void sgemm_kernel(const float* __restrict__ A, const float* __restrict__ B,
                  const float* __restrict__ bias, const float* __restrict__ dinv,
                  float* __restrict__ outRaw, float* __restrict__ outScaled,
                  int M, int K, int N)
{
    constexpr int THREADS = (BM/TM)*(BN/TN);
    __shared__ float As[BK][BM];   // transposed A tile
    __shared__ float Bs[BK][BN];

    const int tid      = threadIdx.x;
    const int blockRow = blockIdx.y * BM;
    const int blockCol = blockIdx.x * BN;
    const int tx = tid % (BN/TN);
    const int ty = tid / (BN/TN);

    float acc[TM][TN];
    #pragma unroll
    for (int i = 0; i < TM; i++)
        #pragma unroll
        for (int j = 0; j < TN; j++) acc[i][j] = 0.f;

    constexpr int KV = BK/4;                  // float4 per A-tile row
    constexpr int NV = BN/4;                  // float4 per B-tile row
    constexpr int A_PER_T = (BM*BK/4) / THREADS;
    constexpr int B_PER_T = (BK*BN/4) / THREADS;

    for (int k0 = 0; k0 < K; k0 += BK) {
        // load A tile (transposed into As), with optional elementwise transform
        #pragma unroll
        for (int v = 0; v < A_PER_T; v++) {
            int vid = tid + v*THREADS;
            int row = vid / KV;
            int kq  = vid % KV;
            float4 val = make_float4(0.f, 0.f, 0.f, 0.f);
            int grow = blockRow + row;
            if (grow < M)
                val = *(const float4*)(A + (size_t)grow*K + k0 + kq*4);
            if (MODE == 1) {
                int kg = k0 + kq*4;
                val.x = 0.9f*fmaxf(val.x + bias[kg+0], 0.f) + 0.1f;
                val.y = 0.9f*fmaxf(val.y + bias[kg+1], 0.f) + 0.1f;
                val.z = 0.9f*fmaxf(val.z + bias[kg+2], 0.f) + 0.1f;
                val.w = 0.9f*fmaxf(val.w + bias[kg+3], 0.f) + 0.1f;
            }
            As[kq*4+0][row] = val.x;
            As[kq*4+1][row] = val.y;
            As[kq*4+2][row] = val.z;
            As[kq*4+3][row] = val.w;
        }
        // load B tile
        #pragma unroll
        for (int v = 0; v < B_PER_T; v++) {
            int vid  = tid + v*THREADS;
            int rowB = vid / NV;
            int nq   = vid % NV;
            *(float4*)&Bs[rowB][nq*4] =
                *(const float4*)(B + (size_t)(k0+rowB)*N + blockCol + nq*4);
        }
        __syncthreads();

        #pragma unroll
        for (int kk = 0; kk < BK; kk++) {
            float a[TM], b[TN];
            #pragma unroll
            for (int i = 0; i < TM; i++) a[i] = As[kk][ty*TM + i];
            #pragma unroll
            for (int j = 0; j < TN; j++) b[j] = Bs[kk][tx*TN + j];
            #pragma unroll
            for (int i = 0; i < TM; i++)
                #pragma unroll
                for (int j = 0; j < TN; j++)
                    acc[i][j] = fmaf(a[i], b[j], acc[i][j]);
        }
        __syncthreads();
    }

    // epilogue: raw output + dinv^2-scaled output (self-loop accumulator init)
    #pragma unroll
    for (int i = 0; i < TM; i++) {
        int row = blockRow + ty*TM + i;
        if (row >= M) continue;
        float di = dinv[row];
        float d2 = di * di;
        #pragma unroll
        for (int j = 0; j < TN; j += 4) {
            float4 r  = make_float4(acc[i][j], acc[i][j+1], acc[i][j+2], acc[i][j+3]);
            size_t off = (size_t)row*N + blockCol + tx*TN + j;
            *(float4*)(outRaw + off) = r;
            float4 sr = make_float4(d2*r.x, d2*r.y, d2*r.z, d2*r.w);
            *(float4*)(outScaled + off) = sr;
        }
    }
}

// ---------------- edge scatter: acc[dst] += dinv[src]*dinv[dst] * feat[src] ----
// F floats per node row; F/4 lanes per edge, each lane handles one float4
// and issues one vectorized red.global.add.v4.f32 (sm_90+).
template<int F>
__global__ void scatter_kernel(const float* __restrict__ feat,
                               const int* __restrict__ src,
                               const int* __restrict__ dst,
                               const float* __restrict__ dinv,
                               float* __restrict__ acc, int E)
{
    constexpr int LPE = F / 4;  // lanes per edge (32 or 16)
    long long t = (long long)blockIdx.x * blockDim.x + threadIdx.x;
    int e   = (int)(t / LPE);
    int sub = threadIdx.x & (LPE - 1);
    if (e >= E) return;

    int s = 0, d = 0;
    float norm = 0.f;
    if (sub == 0) {
        s = __ldg(src + e);
        d = __ldg(dst + e);
        norm = __ldg(dinv + s) * __ldg(dinv + d);
    }
    s    = __shfl_sync(0xffffffffu, s, 0, LPE);
    d    = __shfl_sync(0xffffffffu, d, 0, LPE);
    norm = __shfl_sync(0xffffffffu, norm, 0, LPE);

    const float4 v = *(const float4*)(feat + (size_t)s*F + sub*4);
    float4 r = make_float4(norm*v.x, norm*v.y, norm*v.z, norm*v.w);
    float* p = acc + (size_t)d*F + sub*4;
    asm volatile("red.global.add.v4.f32 [%0], {%1,%2,%3,%4};"
                 :: "l"(p), "f"(r.x), "f"(r.y), "f"(r.z), "f"(r.w)
                 : "memory");
}

// ---------------- log-softmax over 64 cols, one warp per row ------------------
__global__ void lsm_kernel(const float* __restrict__ acc2, const float* __restrict__ b2,
                           float* __restrict__ out, int n)
{
    int warp = (blockIdx.x * blockDim.x + threadIdx.x) >> 5;
    int lane = threadIdx.x & 31;
    if (warp >= n) return;
    const float* r = acc2 + (size_t)warp * OUTF;
    float v0 = r[lane]      + b2[lane];
    float v1 = r[lane + 32] + b2[lane + 32];
    float m = fmaxf(v0, v1);
    #pragma unroll
    for (int o = 16; o > 0; o >>= 1) m = fmaxf(m, __shfl_xor_sync(0xffffffffu, m, o));
    float s = expf(v0 - m) + expf(v1 - m);
    #pragma unroll
    for (int o = 16; o > 0; o >>= 1) s += __shfl_xor_sync(0xffffffffu, s, o);
    float ls = m + logf(s);
    out[(size_t)warp*OUTF + lane]      = v0 - ls;
    out[(size_t)warp*OUTF + lane + 32] = v1 - ls;
}

// ---------------- launch -------------------------------------------------------
extern "C" void kernel_launch(void* const* d_in, const int* in_sizes, int n_in,
                              void* d_out, int out_size)
{
    const float* x  = (const float*)d_in[0];
    const int*   ei = (const int*)  d_in[1];
    // d_in[2] = edge_weight: provably unused (group_softmax over singleton
    // segments makes the CRF term identically 1.0 for finite inputs).
    const float* W1 = (const float*)d_in[3];
    const float* b1 = (const float*)d_in[4];
    const float* W2 = (const float*)d_in[5];
    const float* b2 = (const float*)d_in[6];
    float* out = (float*)d_out;

    const int HID = in_sizes[4];                 // 128
    const int IN  = in_sizes[3] / HID;           // 256
    const int OUT = in_sizes[6];                 // 64
    const int n   = in_sizes[0] / IN;            // 100000
    const int E   = in_sizes[2];                 // 1600000
    const int* src = ei;
    const int* dst = ei + E;

    float *h, *a1, *g, *a2, *deg, *dinv;
    cudaGetSymbolAddress((void**)&h,    g_h);
    cudaGetSymbolAddress((void**)&a1,   g_acc1);
    cudaGetSymbolAddress((void**)&g,    g_g);
    cudaGetSymbolAddress((void**)&a2,   g_acc2);
    cudaGetSymbolAddress((void**)&deg,  g_deg);
    cudaGetSymbolAddress((void**)&dinv, g_dinv);

    // 1) degrees + dinv
    cudaMemsetAsync(deg, 0, (size_t)n * sizeof(float));
    deg_kernel <<<(E + 255)/256, 256>>>(dst, E, deg);
    dinv_kernel<<<(n + 255)/256, 256>>>(deg, dinv, n);

    // 2) GEMM1: h = x@W1 ; a1 = dinv^2 * h  (self-loop init)
    {
        dim3 grid(HID/128, (n + 127)/128);
        sgemm_kernel<128,128,16,8,8,0><<<grid, 256>>>(x, W1, nullptr, dinv, h, a1, n, IN, HID);
    }

    // 3) scatter1: a1[dst] += dinv[s]*dinv[d] * h[src]   (128 floats/edge)
    {
        long long T = (long long)E * (HIDF/4);
        scatter_kernel<HIDF><<<(unsigned)((T + 255)/256), 256>>>(h, src, dst, dinv, a1, E);
    }

    // 4) GEMM2 with fused h2 = 0.9*relu(a1+b1)+0.1 on A-load:
    //    g = h2@W2 ; a2 = dinv^2 * g
    {
        dim3 grid(OUT/64, (n + 127)/128);
        sgemm_kernel<128,64,16,8,4,1><<<grid, 256>>>(a1, W2, b1, dinv, g, a2, n, HID, OUT);
    }

    // 5) scatter2: a2[dst] += norm * g[src]   (64 floats/edge)
    {
        long long T = (long long)E * (OUTF/4);
        scatter_kernel<OUTF><<<(unsigned)((T + 255)/256), 256>>>(g, src, dst, dinv, a2, E);
    }

    // 6) out = log_softmax(a2 + b2)
    lsm_kernel<<<((long long)n*32 + 255)/256, 256>>>(a2, b2, out, n);
}

// round 2
// speedup vs baseline: 1.5337x; 1.5337x over previous
#include <cuda_runtime.h>
#include <cstdint>

#define MAX_NODES 100000
#define MAX_EDGES 1600000
#define HIDF 128
#define OUTF 64
#define SCAN_BS 1024

// ---------------- device scratch ----------------------------------------------
__device__ __align__(128) float g_h  [(size_t)MAX_NODES * HIDF]; // x@W1
__device__ __align__(128) float g_h2 [(size_t)MAX_NODES * HIDF]; // post gcn1+relu+mix
__device__ __align__(128) float g_g  [(size_t)MAX_NODES * OUTF]; // h2@W2
__device__ __align__(128) float g_dinv[MAX_NODES];
__device__ __align__(128) int   g_cnt   [MAX_NODES];
__device__ __align__(128) int   g_rowptr[MAX_NODES + 1];
__device__ __align__(128) int   g_cursor[MAX_NODES];
__device__ __align__(128) int   g_adj   [MAX_EDGES];     // src ids grouped by dst
__device__ __align__(128) int   g_bsum  [256];           // block sums for scan
__device__ __align__(128) int   g_boff  [256];           // exclusive block offsets

// ---------------- degree histogram --------------------------------------------
__global__ void count_kernel(const int* __restrict__ dst, int E, int* __restrict__ cnt) {
    int i = blockIdx.x * blockDim.x + threadIdx.x;
    if (i < E) atomicAdd(&cnt[dst[i]], 1);
}

__global__ void dinv_kernel(const int* __restrict__ cnt, float* __restrict__ dinv, int n) {
    int i = blockIdx.x * blockDim.x + threadIdx.x;
    if (i < n) dinv[i] = rsqrtf((float)cnt[i] + 1.0f);
}

// ---------------- scan stage A: per-block sums ---------------------------------
__global__ void scanA_kernel(const int* __restrict__ cnt, int n, int* __restrict__ bsum) {
    int i = blockIdx.x * SCAN_BS + threadIdx.x;
    int c = (i < n) ? cnt[i] : 0;
    int lane = threadIdx.x & 31, wid = threadIdx.x >> 5;
    #pragma unroll
    for (int o = 16; o > 0; o >>= 1) c += __shfl_xor_sync(~0u, c, o);
    __shared__ int ws[32];
    if (lane == 0) ws[wid] = c;
    __syncthreads();
    if (threadIdx.x < 32) {
        int v = ws[threadIdx.x];
        #pragma unroll
        for (int o = 16; o > 0; o >>= 1) v += __shfl_xor_sync(~0u, v, o);
        if (threadIdx.x == 0) bsum[blockIdx.x] = v;
    }
}

// ---------------- scan stage B: exclusive scan of block sums (1 thread) --------
__global__ void scanB_kernel(const int* __restrict__ bsum, int nb,
                             int* __restrict__ boff, int* __restrict__ rowptr,
                             int n, int E) {
    if (blockIdx.x == 0 && threadIdx.x == 0) {
        int run = 0;
        for (int b = 0; b < nb; b++) { boff[b] = run; run += bsum[b]; }
        rowptr[n] = E;
    }
}

// ---------------- scan stage C: per-element exclusive scan + offset ------------
__global__ void scanC_kernel(const int* __restrict__ cnt, const int* __restrict__ boff,
                             int n, int* __restrict__ rowptr, int* __restrict__ cursor) {
    int i = blockIdx.x * SCAN_BS + threadIdx.x;
    int c = (i < n) ? cnt[i] : 0;
    int lane = threadIdx.x & 31, wid = threadIdx.x >> 5;
    int v = c;
    #pragma unroll
    for (int o = 1; o < 32; o <<= 1) {
        int t = __shfl_up_sync(~0u, v, o);
        if (lane >= o) v += t;
    }
    __shared__ int ws[32];
    if (lane == 31) ws[wid] = v;
    __syncthreads();
    if (threadIdx.x < 32) {
        int w = ws[threadIdx.x];
        #pragma unroll
        for (int o = 1; o < 32; o <<= 1) {
            int t = __shfl_up_sync(~0u, w, o);
            if ((int)threadIdx.x >= o) w += t;
        }
        ws[threadIdx.x] = w;
    }
    __syncthreads();
    int excl = v - c + (wid > 0 ? ws[wid - 1] : 0) + boff[blockIdx.x];
    if (i < n) { rowptr[i] = excl; cursor[i] = excl; }
}

// ---------------- CSR fill -----------------------------------------------------
__global__ void fill_kernel(const int* __restrict__ src, const int* __restrict__ dst,
                            int E, int* __restrict__ cursor, int* __restrict__ adj) {
    int i = blockIdx.x * blockDim.x + threadIdx.x;
    if (i < E) {
        int pos = atomicAdd(&cursor[dst[i]], 1);
        adj[pos] = src[i];
    }
}

// ---------------- tiled SGEMM (raw output only) --------------------------------
template<int BM, int BN, int BK, int TM, int TN>
__global__ __launch_bounds__((BM/TM)*(BN/TN))
void sgemm_kernel(const float* __restrict__ A, const float* __restrict__ B,
                  float* __restrict__ C, int M, int K, int N)
{
    constexpr int THREADS = (BM/TM)*(BN/TN);
    __shared__ float As[BK][BM];
    __shared__ float Bs[BK][BN];

    const int tid = threadIdx.x;
    const int blockRow = blockIdx.y * BM;
    const int blockCol = blockIdx.x * BN;
    const int tx = tid % (BN/TN);
    const int ty = tid / (BN/TN);

    float acc[TM][TN];
    #pragma unroll
    for (int i = 0; i < TM; i++)
        #pragma unroll
        for (int j = 0; j < TN; j++) acc[i][j] = 0.f;

    constexpr int KV = BK/4;
    constexpr int NV = BN/4;
    constexpr int A_PER_T = (BM*BK/4) / THREADS;
    constexpr int B_PER_T = (BK*BN/4) / THREADS;

    for (int k0 = 0; k0 < K; k0 += BK) {
        #pragma unroll
        for (int v = 0; v < A_PER_T; v++) {
            int vid = tid + v*THREADS;
            int row = vid / KV;
            int kq  = vid % KV;
            float4 val = make_float4(0.f, 0.f, 0.f, 0.f);
            int grow = blockRow + row;
            if (grow < M)
                val = *(const float4*)(A + (size_t)grow*K + k0 + kq*4);
            As[kq*4+0][row] = val.x;
            As[kq*4+1][row] = val.y;
            As[kq*4+2][row] = val.z;
            As[kq*4+3][row] = val.w;
        }
        #pragma unroll
        for (int v = 0; v < B_PER_T; v++) {
            int vid  = tid + v*THREADS;
            int rowB = vid / NV;
            int nq   = vid % NV;
            *(float4*)&Bs[rowB][nq*4] =
                *(const float4*)(B + (size_t)(k0+rowB)*N + blockCol + nq*4);
        }
        __syncthreads();

        #pragma unroll
        for (int kk = 0; kk < BK; kk++) {
            float a[TM], b[TN];
            #pragma unroll
            for (int i = 0; i < TM; i++) a[i] = As[kk][ty*TM + i];
            #pragma unroll
            for (int j = 0; j < TN; j++) b[j] = Bs[kk][tx*TN + j];
            #pragma unroll
            for (int i = 0; i < TM; i++)
                #pragma unroll
                for (int j = 0; j < TN; j++)
                    acc[i][j] = fmaf(a[i], b[j], acc[i][j]);
        }
        __syncthreads();
    }

    #pragma unroll
    for (int i = 0; i < TM; i++) {
        int row = blockRow + ty*TM + i;
        if (row >= M) continue;
        #pragma unroll
        for (int j = 0; j < TN; j += 4) {
            float4 r = make_float4(acc[i][j], acc[i][j+1], acc[i][j+2], acc[i][j+3]);
            *(float4*)(C + (size_t)row*N + blockCol + tx*TN + j) = r;
        }
    }
}

// ---------------- agg1: gcn1 aggregate + self + bias + relu + CRF mix ----------
// one warp per node; lane handles features [lane*4, lane*4+4)
__global__ void agg1_kernel(const float* __restrict__ h, const int* __restrict__ rowptr,
                            const int* __restrict__ adj, const float* __restrict__ dinv,
                            const float* __restrict__ b1, float* __restrict__ h2, int n)
{
    int node = (blockIdx.x * blockDim.x + threadIdx.x) >> 5;
    int lane = threadIdx.x & 31;
    if (node >= n) return;

    int beg = rowptr[node];
    int end = rowptr[node + 1];
    float dd = dinv[node];
    size_t l4 = (size_t)lane * 4;

    float ax = 0.f, ay = 0.f, az = 0.f, aw = 0.f;
    int e = beg;
    for (; e + 1 < end; e += 2) {
        int s0 = __ldg(adj + e);
        int s1 = __ldg(adj + e + 1);
        float n0 = __ldg(dinv + s0) * dd;
        float n1 = __ldg(dinv + s1) * dd;
        float4 v0 = *(const float4*)(h + (size_t)s0 * HIDF + l4);
        float4 v1 = *(const float4*)(h + (size_t)s1 * HIDF + l4);
        ax = fmaf(n0, v0.x, ax); ay = fmaf(n0, v0.y, ay);
        az = fmaf(n0, v0.z, az); aw = fmaf(n0, v0.w, aw);
        ax = fmaf(n1, v1.x, ax); ay = fmaf(n1, v1.y, ay);
        az = fmaf(n1, v1.z, az); aw = fmaf(n1, v1.w, aw);
    }
    if (e < end) {
        int s0 = __ldg(adj + e);
        float n0 = __ldg(dinv + s0) * dd;
        float4 v0 = *(const float4*)(h + (size_t)s0 * HIDF + l4);
        ax = fmaf(n0, v0.x, ax); ay = fmaf(n0, v0.y, ay);
        az = fmaf(n0, v0.z, az); aw = fmaf(n0, v0.w, aw);
    }

    float d2 = dd * dd;
    float4 hv = *(const float4*)(h + (size_t)node * HIDF + l4);
    float4 bv = *(const float4*)(b1 + l4);
    float tx_ = fmaf(d2, hv.x, ax) + bv.x;
    float ty_ = fmaf(d2, hv.y, ay) + bv.y;
    float tz_ = fmaf(d2, hv.z, az) + bv.z;
    float tw_ = fmaf(d2, hv.w, aw) + bv.w;
    float4 o;
    o.x = 0.9f * fmaxf(tx_, 0.f) + 0.1f;
    o.y = 0.9f * fmaxf(ty_, 0.f) + 0.1f;
    o.z = 0.9f * fmaxf(tz_, 0.f) + 0.1f;
    o.w = 0.9f * fmaxf(tw_, 0.f) + 0.1f;
    *(float4*)(h2 + (size_t)node * HIDF + l4) = o;
}

// ---------------- agg2: gcn2 aggregate + self + bias + log-softmax -------------
// 16 lanes per node (2 nodes per warp); lane handles features [sub*4, sub*4+4)
__global__ void agg2_kernel(const float* __restrict__ g, const int* __restrict__ rowptr,
                            const int* __restrict__ adj, const float* __restrict__ dinv,
                            const float* __restrict__ b2, float* __restrict__ out, int n)
{
    int node = (blockIdx.x * blockDim.x + threadIdx.x) >> 4;
    int sub  = threadIdx.x & 15;
    if (node >= n) return;

    int beg = rowptr[node];
    int end = rowptr[node + 1];
    float dd = dinv[node];
    size_t l4 = (size_t)sub * 4;

    float ax = 0.f, ay = 0.f, az = 0.f, aw = 0.f;
    int e = beg;
    for (; e + 1 < end; e += 2) {
        int s0 = __ldg(adj + e);
        int s1 = __ldg(adj + e + 1);
        float n0 = __ldg(dinv + s0) * dd;
        float n1 = __ldg(dinv + s1) * dd;
        float4 v0 = *(const float4*)(g + (size_t)s0 * OUTF + l4);
        float4 v1 = *(const float4*)(g + (size_t)s1 * OUTF + l4);
        ax = fmaf(n0, v0.x, ax); ay = fmaf(n0, v0.y, ay);
        az = fmaf(n0, v0.z, az); aw = fmaf(n0, v0.w, aw);
        ax = fmaf(n1, v1.x, ax); ay = fmaf(n1, v1.y, ay);
        az = fmaf(n1, v1.z, az); aw = fmaf(n1, v1.w, aw);
    }
    if (e < end) {
        int s0 = __ldg(adj + e);
        float n0 = __ldg(dinv + s0) * dd;
        float4 v0 = *(const float4*)(g + (size_t)s0 * OUTF + l4);
        ax = fmaf(n0, v0.x, ax); ay = fmaf(n0, v0.y, ay);
        az = fmaf(n0, v0.z, az); aw = fmaf(n0, v0.w, aw);
    }

    float d2 = dd * dd;
    float4 gv = *(const float4*)(g + (size_t)node * OUTF + l4);
    float4 bv = *(const float4*)(b2 + l4);
    float v0 = fmaf(d2, gv.x, ax) + bv.x;
    float v1 = fmaf(d2, gv.y, ay) + bv.y;
    float v2 = fmaf(d2, gv.z, az) + bv.z;
    float v3 = fmaf(d2, gv.w, aw) + bv.w;

    // log-softmax over the 64 values owned by this 16-lane group
    float m = fmaxf(fmaxf(v0, v1), fmaxf(v2, v3));
    #pragma unroll
    for (int o = 8; o > 0; o >>= 1) m = fmaxf(m, __shfl_xor_sync(~0u, m, o, 16));
    float s = expf(v0 - m) + expf(v1 - m) + expf(v2 - m) + expf(v3 - m);
    #pragma unroll
    for (int o = 8; o > 0; o >>= 1) s += __shfl_xor_sync(~0u, s, o, 16);
    float ls = m + logf(s);

    float4 r = make_float4(v0 - ls, v1 - ls, v2 - ls, v3 - ls);
    *(float4*)(out + (size_t)node * OUTF + l4) = r;
}

// ---------------- launch --------------------------------------------------------
extern "C" void kernel_launch(void* const* d_in, const int* in_sizes, int n_in,
                              void* d_out, int out_size)
{
    const float* x  = (const float*)d_in[0];
    const int*   ei = (const int*)  d_in[1];
    // d_in[2] edge_weight: unused (CRF softmax over singleton groups == 1.0)
    const float* W1 = (const float*)d_in[3];
    const float* b1 = (const float*)d_in[4];
    const float* W2 = (const float*)d_in[5];
    const float* b2 = (const float*)d_in[6];
    float* out = (float*)d_out;

    const int HID = in_sizes[4];          // 128
    const int IN  = in_sizes[3] / HID;    // 256
    const int OUT = in_sizes[6];          // 64
    const int n   = in_sizes[0] / IN;     // 100000
    const int E   = in_sizes[2];          // 1600000
    const int* src = ei;
    const int* dst = ei + E;

    float *h, *h2, *g, *dinv;
    int *cnt, *rowptr, *cursor, *adj, *bsum, *boff;
    cudaGetSymbolAddress((void**)&h,     g_h);
    cudaGetSymbolAddress((void**)&h2,    g_h2);
    cudaGetSymbolAddress((void**)&g,     g_g);
    cudaGetSymbolAddress((void**)&dinv,  g_dinv);
    cudaGetSymbolAddress((void**)&cnt,   g_cnt);
    cudaGetSymbolAddress((void**)&rowptr,g_rowptr);
    cudaGetSymbolAddress((void**)&cursor,g_cursor);
    cudaGetSymbolAddress((void**)&adj,   g_adj);
    cudaGetSymbolAddress((void**)&bsum,  g_bsum);
    cudaGetSymbolAddress((void**)&boff,  g_boff);

    const int nb = (n + SCAN_BS - 1) / SCAN_BS;

    // CSR build + dinv
    cudaMemsetAsync(cnt, 0, (size_t)n * sizeof(int));
    count_kernel<<<(E + 255)/256, 256>>>(dst, E, cnt);
    dinv_kernel <<<(n + 255)/256, 256>>>(cnt, dinv, n);
    scanA_kernel<<<nb, SCAN_BS>>>(cnt, n, bsum);
    scanB_kernel<<<1, 32>>>(bsum, nb, boff, rowptr, n, E);
    scanC_kernel<<<nb, SCAN_BS>>>(cnt, boff, n, rowptr, cursor);
    fill_kernel <<<(E + 255)/256, 256>>>(src, dst, E, cursor, adj);

    // GEMM1: h = x @ W1
    {
        dim3 grid(HID/128, (n + 127)/128);
        sgemm_kernel<128,128,16,8,8><<<grid, 256>>>(x, W1, h, n, IN, HID);
    }

    // agg1: h2 = 0.9*relu(agg(norm*h) + dinv^2*h + b1) + 0.1
    agg1_kernel<<<((long long)n*32 + 255)/256, 256>>>(h, rowptr, adj, dinv, b1, h2, n);

    // GEMM2: g = h2 @ W2
    {
        dim3 grid(OUT/64, (n + 127)/128);
        sgemm_kernel<128,64,16,8,4><<<grid, 256>>>(h2, W2, g, n, HID, OUT);
    }

    // agg2: out = log_softmax(agg(norm*g) + dinv^2*g + b2)
    agg2_kernel<<<((long long)n*16 + 255)/256, 256>>>(g, rowptr, adj, dinv, b2, out, n);
}

// round 4
// speedup vs baseline: 2.1826x; 1.4231x over previous
#include <cuda_runtime.h>
#include <cuda_bf16.h>
#include <cstdint>

#define MAX_NODES 100000
#define MAX_EDGES 1600000
#define INF  256
#define HIDF 128
#define OUTF 64
#define SCAN_BS 1024

// ---------------- device scratch ----------------------------------------------
__device__ __align__(128) float g_h  [(size_t)MAX_NODES * HIDF];
__device__ __align__(128) float g_h2 [(size_t)MAX_NODES * HIDF];
__device__ __align__(128) float g_g  [(size_t)MAX_NODES * OUTF];
__device__ __align__(128) float g_dinv[MAX_NODES];
__device__ __align__(128) int   g_cnt   [MAX_NODES];
__device__ __align__(128) int   g_rowptr[MAX_NODES + 1];
__device__ __align__(128) int   g_cursor[MAX_NODES];
__device__ __align__(128) int   g_adj   [MAX_EDGES];
__device__ __align__(128) int   g_bsum  [256];
__device__ __align__(128) int   g_boff  [256];
// weight images: swizzled bf16, chunked [k/64][n rows][64 k], SW128 within 128B row
__device__ __align__(128) __nv_bfloat16 g_w1hi[INF * HIDF];
__device__ __align__(128) __nv_bfloat16 g_w1lo[INF * HIDF];
__device__ __align__(128) __nv_bfloat16 g_w2hi[HIDF * OUTF];
__device__ __align__(128) __nv_bfloat16 g_w2lo[HIDF * OUTF];

// ================= warp-MMA helpers (sm_80+ baseline; no 'a' features) =========
__device__ __forceinline__ uint32_t smem_u32(const void* p) {
    uint32_t a;
    asm("{ .reg .u64 t; cvta.to.shared.u64 t, %1; cvt.u32.u64 %0, t; }" : "=r"(a) : "l"(p));
    return a;
}
__device__ __forceinline__ void ldsm_x4(uint32_t* r, uint32_t addr) {
    asm volatile("ldmatrix.sync.aligned.m8n8.x4.shared.b16 {%0,%1,%2,%3}, [%4];"
                 : "=r"(r[0]), "=r"(r[1]), "=r"(r[2]), "=r"(r[3]) : "r"(addr));
}
__device__ __forceinline__ void ldsm_x2(uint32_t* r, uint32_t addr) {
    asm volatile("ldmatrix.sync.aligned.m8n8.x2.shared.b16 {%0,%1}, [%2];"
                 : "=r"(r[0]), "=r"(r[1]) : "r"(addr));
}
__device__ __forceinline__ void mma_bf16(float* d, const uint32_t* a, const uint32_t* b) {
    asm volatile(
        "mma.sync.aligned.m16n8k16.row.col.f32.bf16.bf16.f32 "
        "{%0,%1,%2,%3}, {%4,%5,%6,%7}, {%8,%9}, {%0,%1,%2,%3};"
        : "+f"(d[0]), "+f"(d[1]), "+f"(d[2]), "+f"(d[3])
        : "r"(a[0]), "r"(a[1]), "r"(a[2]), "r"(a[3]), "r"(b[0]), "r"(b[1]));
}

// ================= CSR build ====================================================
__global__ void count_kernel(const int* __restrict__ dst, int E, int* __restrict__ cnt) {
    int i = blockIdx.x * blockDim.x + threadIdx.x;
    if (i < E) atomicAdd(&cnt[dst[i]], 1);
}
__global__ void dinv_kernel(const int* __restrict__ cnt, float* __restrict__ dinv, int n) {
    int i = blockIdx.x * blockDim.x + threadIdx.x;
    if (i < n) dinv[i] = rsqrtf((float)cnt[i] + 1.0f);
}
__global__ void scanA_kernel(const int* __restrict__ cnt, int n, int* __restrict__ bsum) {
    int i = blockIdx.x * SCAN_BS + threadIdx.x;
    int c = (i < n) ? cnt[i] : 0;
    int lane = threadIdx.x & 31, wid = threadIdx.x >> 5;
    #pragma unroll
    for (int o = 16; o > 0; o >>= 1) c += __shfl_xor_sync(~0u, c, o);
    __shared__ int ws[32];
    if (lane == 0) ws[wid] = c;
    __syncthreads();
    if (threadIdx.x < 32) {
        int v = ws[threadIdx.x];
        #pragma unroll
        for (int o = 16; o > 0; o >>= 1) v += __shfl_xor_sync(~0u, v, o);
        if (threadIdx.x == 0) bsum[blockIdx.x] = v;
    }
}
__global__ void scanB_kernel(const int* __restrict__ bsum, int nb,
                             int* __restrict__ boff, int* __restrict__ rowptr,
                             int n, int E) {
    int t = threadIdx.x;                       // 128 threads, nb <= 128
    int v = (t < nb) ? bsum[t] : 0;
    int lane = t & 31, w = t >> 5;
    int incl = v;
    #pragma unroll
    for (int o = 1; o < 32; o <<= 1) {
        int u = __shfl_up_sync(~0u, incl, o);
        if (lane >= o) incl += u;
    }
    __shared__ int ws[4];
    if (lane == 31) ws[w] = incl;
    __syncthreads();
    int add = 0;
    #pragma unroll
    for (int k = 0; k < 4; k++) if (k < w) add += ws[k];
    if (t < nb) boff[t] = incl - v + add;
    if (t == 0) rowptr[n] = E;
}
__global__ void scanC_kernel(const int* __restrict__ cnt, const int* __restrict__ boff,
                             int n, int* __restrict__ rowptr, int* __restrict__ cursor) {
    int i = blockIdx.x * SCAN_BS + threadIdx.x;
    int c = (i < n) ? cnt[i] : 0;
    int lane = threadIdx.x & 31, wid = threadIdx.x >> 5;
    int v = c;
    #pragma unroll
    for (int o = 1; o < 32; o <<= 1) {
        int t = __shfl_up_sync(~0u, v, o);
        if (lane >= o) v += t;
    }
    __shared__ int ws[32];
    if (lane == 31) ws[wid] = v;
    __syncthreads();
    if (threadIdx.x < 32) {
        int w = ws[threadIdx.x];
        #pragma unroll
        for (int o = 1; o < 32; o <<= 1) {
            int t = __shfl_up_sync(~0u, w, o);
            if ((int)threadIdx.x >= o) w += t;
        }
        ws[threadIdx.x] = w;
    }
    __syncthreads();
    int excl = v - c + (wid > 0 ? ws[wid - 1] : 0) + boff[blockIdx.x];
    if (i < n) { rowptr[i] = excl; cursor[i] = excl; }
}
__global__ void fill_kernel(const int* __restrict__ src, const int* __restrict__ dst,
                            int E, int* __restrict__ cursor, int* __restrict__ adj) {
    int i = blockIdx.x * blockDim.x + threadIdx.x;
    if (i < E) {
        int pos = atomicAdd(&cursor[dst[i]], 1);
        adj[pos] = src[i];
    }
}

// ================= weight prep: W[K,N] -> swizzled bf16 hi/lo image ============
__global__ void wsplit_kernel(const float* __restrict__ W, int K, int N,
                              __nv_bfloat16* __restrict__ hi, __nv_bfloat16* __restrict__ lo) {
    int idx = blockIdx.x * blockDim.x + threadIdx.x;
    if (idx >= K * N) return;
    int k = idx / N, n = idx % N;
    float w = W[(size_t)k * N + n];
    __nv_bfloat16 h = __float2bfloat16(w);
    __nv_bfloat16 l = __float2bfloat16(w - __bfloat162float(h));
    int c = k >> 6, kk = k & 63;
    uint32_t off = (uint32_t)(n * 128 + kk * 2);
    uint32_t sw = off ^ ((off >> 3) & 0x70);
    size_t pos = ((size_t)c * N * 128 + sw) / 2;     // bf16 element index
    hi[pos] = h;
    lo[pos] = l;
}

// ================= warp-MMA GEMM: C[M,NT] = A[M,KCH*64] @ Wimg^T ===============
// bf16 hi/lo split (3 terms), fp32 accum via mma.sync.m16n8k16.
// 256 threads = 8 warps: warp_m = wid&1 (64 rows), warp_n = wid>>1 (NT/4 cols).
// Whole weight image in SMEM; A tile double-buffered (16KB hi + 16KB lo each).
template<int NT, int KCH>
__global__ __launch_bounds__(256, 1)
void mma_gemm(const float* __restrict__ A, int lda,
              const __nv_bfloat16* __restrict__ imgHi, const __nv_bfloat16* __restrict__ imgLo,
              float* __restrict__ C, int M)
{
    constexpr int BCH = NT * 128;            // bytes per weight chunk (per array)
    constexpr int BB  = KCH * BCH;           // weight bytes per array
    constexpr int OFF_BHI = 0;
    constexpr int OFF_BLO = BB;
    constexpr int OFF_A   = 2 * BB;          // 2 bufs x (hi 16KB + lo 16KB)
    constexpr int NTW = NT / 4;              // cols per warp
    constexpr int NF  = NTW / 8;             // n-frags per warp

    extern __shared__ char smraw[];
    char* sp = (char*)((((uintptr_t)smraw) + 1023) & ~(uintptr_t)1023);
    const uint32_t sb = smem_u32(sp);

    const int tid = threadIdx.x;
    const int wid = tid >> 5;
    const int l   = tid & 31;
    const int blockRow = blockIdx.x * 128;
    const int warp_m = wid & 1;
    const int warp_n = wid >> 1;

    // copy swizzled weight images into SMEM
    {
        const uint4* shi = (const uint4*)imgHi;
        const uint4* slo = (const uint4*)imgLo;
        uint4* dhi = (uint4*)(sp + OFF_BHI);
        uint4* dlo = (uint4*)(sp + OFF_BLO);
        for (int i = tid; i < BB / 16; i += 256) { dhi[i] = shi[i]; dlo[i] = slo[i]; }
    }

    float acc[4][NF][4];
    #pragma unroll
    for (int i = 0; i < 4; i++)
        #pragma unroll
        for (int j = 0; j < NF; j++)
            #pragma unroll
            for (int q = 0; q < 4; q++) acc[i][j][q] = 0.f;

    // per-lane ldmatrix address constants (swizzle xor depends only on row%8)
    const uint32_t xorm = (uint32_t)(l & 7) << 4;
    const uint32_t aRow = warp_m * 64 + (l & 15);
    const uint32_t aK8  = (uint32_t)(l >> 4) * 8;
    const uint32_t bN   = warp_n * NTW + (l & 7);
    const uint32_t bK8  = (uint32_t)((l >> 3) & 1) * 8;

    // prefetch A chunk 0 into regs
    float4 pf[8];
    #pragma unroll
    for (int v = 0; v < 8; v++) {
        int vid = tid + v * 256;
        int grow = blockRow + (vid >> 4);
        pf[v] = make_float4(0.f, 0.f, 0.f, 0.f);
        if (grow < M) pf[v] = *(const float4*)(A + (size_t)grow * lda + (vid & 15) * 4);
    }

    for (int c = 0; c < KCH; c++) {
        const int buf = c & 1;
        char* aBase = sp + OFF_A + buf * 32768;
        // convert prefetched fp32 -> bf16 hi/lo, store swizzled
        #pragma unroll
        for (int v = 0; v < 8; v++) {
            int vid = tid + v * 256;
            int row = vid >> 4;
            int kq  = vid & 15;
            float4 xv = pf[v];
            __nv_bfloat16 h0 = __float2bfloat16(xv.x), h1 = __float2bfloat16(xv.y);
            __nv_bfloat16 h2 = __float2bfloat16(xv.z), h3 = __float2bfloat16(xv.w);
            __nv_bfloat16 l0 = __float2bfloat16(xv.x - __bfloat162float(h0));
            __nv_bfloat16 l1 = __float2bfloat16(xv.y - __bfloat162float(h1));
            __nv_bfloat16 l2 = __float2bfloat16(xv.z - __bfloat162float(h2));
            __nv_bfloat16 l3 = __float2bfloat16(xv.w - __bfloat162float(h3));
            uint32_t hi01 = ((uint32_t)__bfloat16_as_ushort(h1) << 16) | __bfloat16_as_ushort(h0);
            uint32_t hi23 = ((uint32_t)__bfloat16_as_ushort(h3) << 16) | __bfloat16_as_ushort(h2);
            uint32_t lo01 = ((uint32_t)__bfloat16_as_ushort(l1) << 16) | __bfloat16_as_ushort(l0);
            uint32_t lo23 = ((uint32_t)__bfloat16_as_ushort(l3) << 16) | __bfloat16_as_ushort(l2);
            uint32_t off = (uint32_t)(row * 128 + kq * 8);
            uint32_t sw = off ^ ((off >> 3) & 0x70);
            *(uint2*)(aBase + sw)         = make_uint2(hi01, hi23);
            *(uint2*)(aBase + 16384 + sw) = make_uint2(lo01, lo23);
        }
        __syncthreads();

        // prefetch next A chunk (overlaps with MMA below)
        if (c + 1 < KCH) {
            #pragma unroll
            for (int v = 0; v < 8; v++) {
                int vid = tid + v * 256;
                int grow = blockRow + (vid >> 4);
                pf[v] = make_float4(0.f, 0.f, 0.f, 0.f);
                if (grow < M)
                    pf[v] = *(const float4*)(A + (size_t)grow * lda + (c + 1) * 64 + (vid & 15) * 4);
            }
        }

        // compute: 4 k-steps of 16 within this 64-wide chunk
        const uint32_t aHiBase = sb + OFF_A + buf * 32768 + aRow * 128;
        const uint32_t aLoBase = aHiBase + 16384;
        const uint32_t bHiBase = sb + OFF_BHI + c * BCH + bN * 128;
        const uint32_t bLoBase = bHiBase + (OFF_BLO - OFF_BHI);
        #pragma unroll
        for (int s = 0; s < 4; s++) {
            const uint32_t akOff = ((uint32_t)(s * 16 + aK8) * 2) ^ xorm;
            const uint32_t bkOff = ((uint32_t)(s * 16 + bK8) * 2) ^ xorm;
            uint32_t bh[NF][2], bl[NF][2];
            #pragma unroll
            for (int j = 0; j < NF; j++) {
                ldsm_x2(bh[j], bHiBase + j * 1024 + bkOff);
                ldsm_x2(bl[j], bLoBase + j * 1024 + bkOff);
            }
            #pragma unroll
            for (int i = 0; i < 4; i++) {
                uint32_t ah[4], al[4];
                ldsm_x4(ah, aHiBase + i * 2048 + akOff);
                ldsm_x4(al, aLoBase + i * 2048 + akOff);
                #pragma unroll
                for (int j = 0; j < NF; j++) {
                    mma_bf16(acc[i][j], ah, bh[j]);
                    mma_bf16(acc[i][j], ah, bl[j]);
                    mma_bf16(acc[i][j], al, bh[j]);
                }
            }
        }
        __syncthreads();
    }

    // epilogue: C fragment layout: c0,c1 @ (row g, col 2t), c2,c3 @ (row g+8)
    const int g = l >> 2;
    const int t2 = (l & 3) * 2;
    #pragma unroll
    for (int i = 0; i < 4; i++) {
        int row0 = blockRow + warp_m * 64 + i * 16 + g;
        #pragma unroll
        for (int j = 0; j < NF; j++) {
            int col = warp_n * NTW + j * 8 + t2;
            if (row0 < M)
                *(float2*)(C + (size_t)row0 * NT + col) = make_float2(acc[i][j][0], acc[i][j][1]);
            if (row0 + 8 < M)
                *(float2*)(C + (size_t)(row0 + 8) * NT + col) = make_float2(acc[i][j][2], acc[i][j][3]);
        }
    }
}

// ================= agg1 ========================================================
__global__ void agg1_kernel(const float* __restrict__ h, const int* __restrict__ rowptr,
                            const int* __restrict__ adj, const float* __restrict__ dinv,
                            const float* __restrict__ b1, float* __restrict__ h2, int n)
{
    int node = (blockIdx.x * blockDim.x + threadIdx.x) >> 5;
    int lane = threadIdx.x & 31;
    if (node >= n) return;
    int beg = rowptr[node], end = rowptr[node + 1];
    float dd = dinv[node];
    size_t l4 = (size_t)lane * 4;
    float ax = 0.f, ay = 0.f, az = 0.f, aw = 0.f;
    int e = beg;
    for (; e + 1 < end; e += 2) {
        int s0 = __ldg(adj + e), s1 = __ldg(adj + e + 1);
        float n0 = __ldg(dinv + s0) * dd, n1 = __ldg(dinv + s1) * dd;
        float4 v0 = *(const float4*)(h + (size_t)s0 * HIDF + l4);
        float4 v1 = *(const float4*)(h + (size_t)s1 * HIDF + l4);
        ax = fmaf(n0, v0.x, ax); ay = fmaf(n0, v0.y, ay);
        az = fmaf(n0, v0.z, az); aw = fmaf(n0, v0.w, aw);
        ax = fmaf(n1, v1.x, ax); ay = fmaf(n1, v1.y, ay);
        az = fmaf(n1, v1.z, az); aw = fmaf(n1, v1.w, aw);
    }
    if (e < end) {
        int s0 = __ldg(adj + e);
        float n0 = __ldg(dinv + s0) * dd;
        float4 v0 = *(const float4*)(h + (size_t)s0 * HIDF + l4);
        ax = fmaf(n0, v0.x, ax); ay = fmaf(n0, v0.y, ay);
        az = fmaf(n0, v0.z, az); aw = fmaf(n0, v0.w, aw);
    }
    float d2 = dd * dd;
    float4 hv = *(const float4*)(h + (size_t)node * HIDF + l4);
    float4 bv = *(const float4*)(b1 + l4);
    float tx_ = fmaf(d2, hv.x, ax) + bv.x;
    float ty_ = fmaf(d2, hv.y, ay) + bv.y;
    float tz_ = fmaf(d2, hv.z, az) + bv.z;
    float tw_ = fmaf(d2, hv.w, aw) + bv.w;
    float4 o;
    o.x = 0.9f * fmaxf(tx_, 0.f) + 0.1f;
    o.y = 0.9f * fmaxf(ty_, 0.f) + 0.1f;
    o.z = 0.9f * fmaxf(tz_, 0.f) + 0.1f;
    o.w = 0.9f * fmaxf(tw_, 0.f) + 0.1f;
    *(float4*)(h2 + (size_t)node * HIDF + l4) = o;
}

// ================= agg2 + log-softmax ==========================================
__global__ void agg2_kernel(const float* __restrict__ g, const int* __restrict__ rowptr,
                            const int* __restrict__ adj, const float* __restrict__ dinv,
                            const float* __restrict__ b2, float* __restrict__ out, int n)
{
    int node = (blockIdx.x * blockDim.x + threadIdx.x) >> 4;
    int sub  = threadIdx.x & 15;
    if (node >= n) return;
    int beg = rowptr[node], end = rowptr[node + 1];
    float dd = dinv[node];
    size_t l4 = (size_t)sub * 4;
    float ax = 0.f, ay = 0.f, az = 0.f, aw = 0.f;
    int e = beg;
    for (; e + 1 < end; e += 2) {
        int s0 = __ldg(adj + e), s1 = __ldg(adj + e + 1);
        float n0 = __ldg(dinv + s0) * dd, n1 = __ldg(dinv + s1) * dd;
        float4 v0 = *(const float4*)(g + (size_t)s0 * OUTF + l4);
        float4 v1 = *(const float4*)(g + (size_t)s1 * OUTF + l4);
        ax = fmaf(n0, v0.x, ax); ay = fmaf(n0, v0.y, ay);
        az = fmaf(n0, v0.z, az); aw = fmaf(n0, v0.w, aw);
        ax = fmaf(n1, v1.x, ax); ay = fmaf(n1, v1.y, ay);
        az = fmaf(n1, v1.z, az); aw = fmaf(n1, v1.w, aw);
    }
    if (e < end) {
        int s0 = __ldg(adj + e);
        float n0 = __ldg(dinv + s0) * dd;
        float4 v0 = *(const float4*)(g + (size_t)s0 * OUTF + l4);
        ax = fmaf(n0, v0.x, ax); ay = fmaf(n0, v0.y, ay);
        az = fmaf(n0, v0.z, az); aw = fmaf(n0, v0.w, aw);
    }
    float d2 = dd * dd;
    float4 gv = *(const float4*)(g + (size_t)node * OUTF + l4);
    float4 bv = *(const float4*)(b2 + l4);
    float v0 = fmaf(d2, gv.x, ax) + bv.x;
    float v1 = fmaf(d2, gv.y, ay) + bv.y;
    float v2 = fmaf(d2, gv.z, az) + bv.z;
    float v3 = fmaf(d2, gv.w, aw) + bv.w;
    float m = fmaxf(fmaxf(v0, v1), fmaxf(v2, v3));
    #pragma unroll
    for (int o = 8; o > 0; o >>= 1) m = fmaxf(m, __shfl_xor_sync(~0u, m, o, 16));
    float s = expf(v0 - m) + expf(v1 - m) + expf(v2 - m) + expf(v3 - m);
    #pragma unroll
    for (int o = 8; o > 0; o >>= 1) s += __shfl_xor_sync(~0u, s, o, 16);
    float ls = m + logf(s);
    float4 r = make_float4(v0 - ls, v1 - ls, v2 - ls, v3 - ls);
    *(float4*)(out + (size_t)node * OUTF + l4) = r;
}

// ================= launch =======================================================
extern "C" void kernel_launch(void* const* d_in, const int* in_sizes, int n_in,
                              void* d_out, int out_size)
{
    const float* x  = (const float*)d_in[0];
    const int*   ei = (const int*)  d_in[1];
    // d_in[2] edge_weight: unused (CRF softmax over singleton groups == 1.0)
    const float* W1 = (const float*)d_in[3];
    const float* b1 = (const float*)d_in[4];
    const float* W2 = (const float*)d_in[5];
    const float* b2 = (const float*)d_in[6];
    float* out = (float*)d_out;

    const int n = in_sizes[0] / INF;
    const int E = in_sizes[2];
    const int* src = ei;
    const int* dst = ei + E;

    float *h, *h2, *g, *dinv;
    int *cnt, *rowptr, *cursor, *adj, *bsum, *boff;
    __nv_bfloat16 *w1hi, *w1lo, *w2hi, *w2lo;
    cudaGetSymbolAddress((void**)&h,     g_h);
    cudaGetSymbolAddress((void**)&h2,    g_h2);
    cudaGetSymbolAddress((void**)&g,     g_g);
    cudaGetSymbolAddress((void**)&dinv,  g_dinv);
    cudaGetSymbolAddress((void**)&cnt,   g_cnt);
    cudaGetSymbolAddress((void**)&rowptr,g_rowptr);
    cudaGetSymbolAddress((void**)&cursor,g_cursor);
    cudaGetSymbolAddress((void**)&adj,   g_adj);
    cudaGetSymbolAddress((void**)&bsum,  g_bsum);
    cudaGetSymbolAddress((void**)&boff,  g_boff);
    cudaGetSymbolAddress((void**)&w1hi,  g_w1hi);
    cudaGetSymbolAddress((void**)&w1lo,  g_w1lo);
    cudaGetSymbolAddress((void**)&w2hi,  g_w2hi);
    cudaGetSymbolAddress((void**)&w2lo,  g_w2lo);

    const int nb = (n + SCAN_BS - 1) / SCAN_BS;

    // dynamic SMEM: weights (2*BB) + A double buffers (64KB) + 1KB align pad
    constexpr int SMEM1 = 2 * (4 * HIDF * 128) + 65536 + 1024;  // ~193KB
    constexpr int SMEM2 = 2 * (2 * OUTF * 128) + 65536 + 1024;  // ~97KB
    cudaFuncSetAttribute(mma_gemm<HIDF, 4>, cudaFuncAttributeMaxDynamicSharedMemorySize, SMEM1);
    cudaFuncSetAttribute(mma_gemm<OUTF, 2>, cudaFuncAttributeMaxDynamicSharedMemorySize, SMEM2);

    // CSR build + dinv + weight prep
    cudaMemsetAsync(cnt, 0, (size_t)n * sizeof(int));
    count_kernel<<<(E + 255)/256, 256>>>(dst, E, cnt);
    dinv_kernel <<<(n + 255)/256, 256>>>(cnt, dinv, n);
    scanA_kernel<<<nb, SCAN_BS>>>(cnt, n, bsum);
    scanB_kernel<<<1, 128>>>(bsum, nb, boff, rowptr, n, E);
    scanC_kernel<<<nb, SCAN_BS>>>(cnt, boff, n, rowptr, cursor);
    fill_kernel <<<(E + 255)/256, 256>>>(src, dst, E, cursor, adj);
    wsplit_kernel<<<(INF*HIDF + 255)/256, 256>>>(W1, INF, HIDF, w1hi, w1lo);
    wsplit_kernel<<<(HIDF*OUTF + 255)/256, 256>>>(W2, HIDF, OUTF, w2hi, w2lo);

    const int mtiles = (n + 127) / 128;

    // GEMM1 (HMMA): h = x @ W1
    mma_gemm<HIDF, 4><<<mtiles, 256, SMEM1>>>(x, INF, w1hi, w1lo, h, n);

    // agg1: h2 = 0.9*relu(agg + dinv^2*h + b1) + 0.1
    agg1_kernel<<<((long long)n*32 + 255)/256, 256>>>(h, rowptr, adj, dinv, b1, h2, n);

    // GEMM2 (HMMA): g = h2 @ W2
    mma_gemm<OUTF, 2><<<mtiles, 256, SMEM2>>>(h2, HIDF, w2hi, w2lo, g, n);

    // agg2: out = log_softmax(agg + dinv^2*g + b2)
    agg2_kernel<<<((long long)n*16 + 255)/256, 256>>>(g, rowptr, adj, dinv, b2, out, n);
}

// round 5
// speedup vs baseline: 2.4236x; 1.1104x over previous
#include <cuda_runtime.h>
#include <cuda_bf16.h>
#include <cstdint>

#define MAX_NODES 100000
#define MAX_EDGES 1600000
#define INF  256
#define HIDF 128
#define OUTF 64
#define SCAN_BS 1024

// ---------------- device scratch ----------------------------------------------
__device__ __align__(128) __nv_bfloat16 g_h  [(size_t)MAX_NODES * HIDF]; // x@W1 (bf16)
__device__ __align__(128) __nv_bfloat16 g_h2 [(size_t)MAX_NODES * HIDF]; // post gcn1 (bf16)
__device__ __align__(128) __nv_bfloat16 g_g  [(size_t)MAX_NODES * OUTF]; // h2@W2 (bf16)
__device__ __align__(128) float g_dinv[MAX_NODES];
__device__ __align__(128) int   g_cnt   [MAX_NODES];
__device__ __align__(128) int   g_rowptr[MAX_NODES + 1];
__device__ __align__(128) int   g_cursor[MAX_NODES];
__device__ __align__(128) int   g_adj   [MAX_EDGES];
__device__ __align__(128) int   g_bsum  [256];
__device__ __align__(128) int   g_boff  [256];
// weight images: swizzled bf16, chunked [k/64][n rows][64 k], SW128 in 128B rows
__device__ __align__(128) __nv_bfloat16 g_w1hi[INF * HIDF];
__device__ __align__(128) __nv_bfloat16 g_w1lo[INF * HIDF];
__device__ __align__(128) __nv_bfloat16 g_w2hi[HIDF * OUTF];
__device__ __align__(128) __nv_bfloat16 g_w2lo[HIDF * OUTF];

// ================= warp-MMA helpers =============================================
__device__ __forceinline__ uint32_t smem_u32(const void* p) {
    uint32_t a;
    asm("{ .reg .u64 t; cvta.to.shared.u64 t, %1; cvt.u32.u64 %0, t; }" : "=r"(a) : "l"(p));
    return a;
}
__device__ __forceinline__ void ldsm_x4(uint32_t* r, uint32_t addr) {
    asm volatile("ldmatrix.sync.aligned.m8n8.x4.shared.b16 {%0,%1,%2,%3}, [%4];"
                 : "=r"(r[0]), "=r"(r[1]), "=r"(r[2]), "=r"(r[3]) : "r"(addr));
}
__device__ __forceinline__ void ldsm_x2(uint32_t* r, uint32_t addr) {
    asm volatile("ldmatrix.sync.aligned.m8n8.x2.shared.b16 {%0,%1}, [%2];"
                 : "=r"(r[0]), "=r"(r[1]) : "r"(addr));
}
__device__ __forceinline__ void mma_bf16(float* d, const uint32_t* a, const uint32_t* b) {
    asm volatile(
        "mma.sync.aligned.m16n8k16.row.col.f32.bf16.bf16.f32 "
        "{%0,%1,%2,%3}, {%4,%5,%6,%7}, {%8,%9}, {%0,%1,%2,%3};"
        : "+f"(d[0]), "+f"(d[1]), "+f"(d[2]), "+f"(d[3])
        : "r"(a[0]), "r"(a[1]), "r"(a[2]), "r"(a[3]), "r"(b[0]), "r"(b[1]));
}
__device__ __forceinline__ float2 bf2f(uint32_t v) {
    return __bfloat1622float2(*reinterpret_cast<__nv_bfloat162*>(&v));
}

// ================= CSR build ====================================================
__global__ void count_kernel(const int* __restrict__ dst, int E, int* __restrict__ cnt) {
    int i = blockIdx.x * blockDim.x + threadIdx.x;
    if (i < E) atomicAdd(&cnt[dst[i]], 1);
}
__global__ void scanA_kernel(const int* __restrict__ cnt, int n, int* __restrict__ bsum) {
    int i = blockIdx.x * SCAN_BS + threadIdx.x;
    int c = (i < n) ? cnt[i] : 0;
    int lane = threadIdx.x & 31, wid = threadIdx.x >> 5;
    #pragma unroll
    for (int o = 16; o > 0; o >>= 1) c += __shfl_xor_sync(~0u, c, o);
    __shared__ int ws[32];
    if (lane == 0) ws[wid] = c;
    __syncthreads();
    if (threadIdx.x < 32) {
        int v = ws[threadIdx.x];
        #pragma unroll
        for (int o = 16; o > 0; o >>= 1) v += __shfl_xor_sync(~0u, v, o);
        if (threadIdx.x == 0) bsum[blockIdx.x] = v;
    }
}
__global__ void scanB_kernel(const int* __restrict__ bsum, int nb,
                             int* __restrict__ boff, int* __restrict__ rowptr,
                             int n, int E) {
    int t = threadIdx.x;
    int v = (t < nb) ? bsum[t] : 0;
    int lane = t & 31, w = t >> 5;
    int incl = v;
    #pragma unroll
    for (int o = 1; o < 32; o <<= 1) {
        int u = __shfl_up_sync(~0u, incl, o);
        if (lane >= o) incl += u;
    }
    __shared__ int ws[4];
    if (lane == 31) ws[w] = incl;
    __syncthreads();
    int add = 0;
    #pragma unroll
    for (int k = 0; k < 4; k++) if (k < w) add += ws[k];
    if (t < nb) boff[t] = incl - v + add;
    if (t == 0) rowptr[n] = E;
}
// scanC also produces dinv (fused)
__global__ void scanC_kernel(const int* __restrict__ cnt, const int* __restrict__ boff,
                             int n, int* __restrict__ rowptr, int* __restrict__ cursor,
                             float* __restrict__ dinv) {
    int i = blockIdx.x * SCAN_BS + threadIdx.x;
    int c = (i < n) ? cnt[i] : 0;
    int lane = threadIdx.x & 31, wid = threadIdx.x >> 5;
    int v = c;
    #pragma unroll
    for (int o = 1; o < 32; o <<= 1) {
        int t = __shfl_up_sync(~0u, v, o);
        if (lane >= o) v += t;
    }
    __shared__ int ws[32];
    if (lane == 31) ws[wid] = v;
    __syncthreads();
    if (threadIdx.x < 32) {
        int w = ws[threadIdx.x];
        #pragma unroll
        for (int o = 1; o < 32; o <<= 1) {
            int t = __shfl_up_sync(~0u, w, o);
            if ((int)threadIdx.x >= o) w += t;
        }
        ws[threadIdx.x] = w;
    }
    __syncthreads();
    int excl = v - c + (wid > 0 ? ws[wid - 1] : 0) + boff[blockIdx.x];
    if (i < n) {
        rowptr[i] = excl;
        cursor[i] = excl;
        dinv[i] = rsqrtf((float)c + 1.0f);
    }
}
__global__ void fill_kernel(const int* __restrict__ src, const int* __restrict__ dst,
                            int E, int* __restrict__ cursor, int* __restrict__ adj) {
    int i = blockIdx.x * blockDim.x + threadIdx.x;
    if (i < E) {
        int pos = atomicAdd(&cursor[dst[i]], 1);
        adj[pos] = src[i];
    }
}

// ================= weight prep ==================================================
__global__ void wsplit_kernel(const float* __restrict__ W, int K, int N,
                              __nv_bfloat16* __restrict__ hi, __nv_bfloat16* __restrict__ lo) {
    int idx = blockIdx.x * blockDim.x + threadIdx.x;
    if (idx >= K * N) return;
    int k = idx / N, n = idx % N;
    float w = W[(size_t)k * N + n];
    __nv_bfloat16 h = __float2bfloat16(w);
    __nv_bfloat16 l = __float2bfloat16(w - __bfloat162float(h));
    int c = k >> 6, kk = k & 63;
    uint32_t off = (uint32_t)(n * 128 + kk * 2);
    uint32_t sw = off ^ ((off >> 3) & 0x70);
    size_t pos = ((size_t)c * N * 128 + sw) / 2;
    hi[pos] = h;
    lo[pos] = l;
}

// ================= warp-MMA GEMM ================================================
// C[M,NT](bf16) = A[M,KCH*64] @ Wimg^T.
// SPLIT_A=true : A fp32, split bf16 hi/lo, 3 MMA terms.
// SPLIT_A=false: A bf16, 2 MMA terms (A·Whi + A·Wlo).
template<int NT, int KCH, bool SPLIT_A>
__global__ __launch_bounds__(256, 1)
void mma_gemm(const void* __restrict__ Ain, int lda,
              const __nv_bfloat16* __restrict__ imgHi, const __nv_bfloat16* __restrict__ imgLo,
              __nv_bfloat16* __restrict__ C, int M)
{
    constexpr int BCH = NT * 128;
    constexpr int BB  = KCH * BCH;
    constexpr int OFF_BHI = 0;
    constexpr int OFF_BLO = BB;
    constexpr int OFF_A   = 2 * BB;
    constexpr int ASTG = SPLIT_A ? 32768 : 16384;   // per-stage A bytes
    constexpr int NTW = NT / 4;
    constexpr int NF  = NTW / 8;

    extern __shared__ char smraw[];
    char* sp = (char*)((((uintptr_t)smraw) + 1023) & ~(uintptr_t)1023);
    const uint32_t sb = smem_u32(sp);

    const int tid = threadIdx.x;
    const int wid = tid >> 5;
    const int l   = tid & 31;
    const int blockRow = blockIdx.x * 128;
    const int warp_m = wid & 1;
    const int warp_n = wid >> 1;

    // weight images -> SMEM
    {
        const uint4* shi = (const uint4*)imgHi;
        const uint4* slo = (const uint4*)imgLo;
        uint4* dhi = (uint4*)(sp + OFF_BHI);
        uint4* dlo = (uint4*)(sp + OFF_BLO);
        for (int i = tid; i < BB / 16; i += 256) { dhi[i] = shi[i]; dlo[i] = slo[i]; }
    }

    float acc[4][NF][4];
    #pragma unroll
    for (int i = 0; i < 4; i++)
        #pragma unroll
        for (int j = 0; j < NF; j++)
            #pragma unroll
            for (int q = 0; q < 4; q++) acc[i][j][q] = 0.f;

    const uint32_t xorm = (uint32_t)(l & 7) << 4;
    const uint32_t aRow = warp_m * 64 + (l & 15);
    const uint32_t aK8  = (uint32_t)(l >> 4) * 8;
    const uint32_t bN   = warp_n * NTW + (l & 7);
    const uint32_t bK8  = (uint32_t)((l >> 3) & 1) * 8;

    const float* Af = (const float*)Ain;
    const __nv_bfloat16* Ab = (const __nv_bfloat16*)Ain;

    float4 pf[8];
    uint4  pb[4];
    // prefetch chunk 0
    if (SPLIT_A) {
        #pragma unroll
        for (int v = 0; v < 8; v++) {
            int vid = tid + v * 256;
            int grow = blockRow + (vid >> 4);
            pf[v] = make_float4(0.f, 0.f, 0.f, 0.f);
            if (grow < M) pf[v] = *(const float4*)(Af + (size_t)grow * lda + (vid & 15) * 4);
        }
    } else {
        #pragma unroll
        for (int v = 0; v < 4; v++) {
            int vid = tid + v * 256;
            int grow = blockRow + (vid >> 3);
            pb[v] = make_uint4(0, 0, 0, 0);
            if (grow < M) pb[v] = *(const uint4*)(Ab + (size_t)grow * lda + (vid & 7) * 8);
        }
    }

    for (int c = 0; c < KCH; c++) {
        const int buf = c & 1;
        char* aBase = sp + OFF_A + buf * ASTG;

        if (SPLIT_A) {
            #pragma unroll
            for (int v = 0; v < 8; v++) {
                int vid = tid + v * 256;
                int row = vid >> 4;
                int kq  = vid & 15;
                float4 xv = pf[v];
                __nv_bfloat16 h0 = __float2bfloat16(xv.x), h1 = __float2bfloat16(xv.y);
                __nv_bfloat16 h2 = __float2bfloat16(xv.z), h3 = __float2bfloat16(xv.w);
                __nv_bfloat16 l0 = __float2bfloat16(xv.x - __bfloat162float(h0));
                __nv_bfloat16 l1 = __float2bfloat16(xv.y - __bfloat162float(h1));
                __nv_bfloat16 l2 = __float2bfloat16(xv.z - __bfloat162float(h2));
                __nv_bfloat16 l3 = __float2bfloat16(xv.w - __bfloat162float(h3));
                uint32_t hi01 = ((uint32_t)__bfloat16_as_ushort(h1) << 16) | __bfloat16_as_ushort(h0);
                uint32_t hi23 = ((uint32_t)__bfloat16_as_ushort(h3) << 16) | __bfloat16_as_ushort(h2);
                uint32_t lo01 = ((uint32_t)__bfloat16_as_ushort(l1) << 16) | __bfloat16_as_ushort(l0);
                uint32_t lo23 = ((uint32_t)__bfloat16_as_ushort(l3) << 16) | __bfloat16_as_ushort(l2);
                uint32_t off = (uint32_t)(row * 128 + kq * 8);
                uint32_t sw = off ^ ((off >> 3) & 0x70);
                *(uint2*)(aBase + sw)         = make_uint2(hi01, hi23);
                *(uint2*)(aBase + 16384 + sw) = make_uint2(lo01, lo23);
            }
        } else {
            #pragma unroll
            for (int v = 0; v < 4; v++) {
                int vid = tid + v * 256;
                int row = vid >> 3;
                int q   = vid & 7;
                uint32_t off = (uint32_t)(row * 128 + q * 16);
                uint32_t sw = off ^ ((off >> 3) & 0x70);
                *(uint4*)(aBase + sw) = pb[v];
            }
        }
        __syncthreads();

        // prefetch next chunk
        if (c + 1 < KCH) {
            if (SPLIT_A) {
                #pragma unroll
                for (int v = 0; v < 8; v++) {
                    int vid = tid + v * 256;
                    int grow = blockRow + (vid >> 4);
                    pf[v] = make_float4(0.f, 0.f, 0.f, 0.f);
                    if (grow < M)
                        pf[v] = *(const float4*)(Af + (size_t)grow * lda + (c + 1) * 64 + (vid & 15) * 4);
                }
            } else {
                #pragma unroll
                for (int v = 0; v < 4; v++) {
                    int vid = tid + v * 256;
                    int grow = blockRow + (vid >> 3);
                    pb[v] = make_uint4(0, 0, 0, 0);
                    if (grow < M)
                        pb[v] = *(const uint4*)(Ab + (size_t)grow * lda + (c + 1) * 64 + (vid & 7) * 8);
                }
            }
        }

        const uint32_t aHiBase = sb + OFF_A + buf * ASTG + aRow * 128;
        const uint32_t aLoBase = aHiBase + 16384;
        const uint32_t bHiBase = sb + OFF_BHI + c * BCH + bN * 128;
        const uint32_t bLoBase = bHiBase + (OFF_BLO - OFF_BHI);
        #pragma unroll
        for (int s = 0; s < 4; s++) {
            const uint32_t akOff = ((uint32_t)(s * 16 + aK8) * 2) ^ xorm;
            const uint32_t bkOff = ((uint32_t)(s * 16 + bK8) * 2) ^ xorm;
            uint32_t bh[NF][2], bl[NF][2];
            #pragma unroll
            for (int j = 0; j < NF; j++) {
                ldsm_x2(bh[j], bHiBase + j * 1024 + bkOff);
                ldsm_x2(bl[j], bLoBase + j * 1024 + bkOff);
            }
            #pragma unroll
            for (int i = 0; i < 4; i++) {
                uint32_t ah[4], al[4];
                ldsm_x4(ah, aHiBase + i * 2048 + akOff);
                if (SPLIT_A) ldsm_x4(al, aLoBase + i * 2048 + akOff);
                #pragma unroll
                for (int j = 0; j < NF; j++) {
                    mma_bf16(acc[i][j], ah, bh[j]);
                    mma_bf16(acc[i][j], ah, bl[j]);
                    if (SPLIT_A) mma_bf16(acc[i][j], al, bh[j]);
                }
            }
        }
        __syncthreads();
    }

    // epilogue: write bf16 (cols pairs are adjacent)
    const int g = l >> 2;
    const int t2 = (l & 3) * 2;
    #pragma unroll
    for (int i = 0; i < 4; i++) {
        int row0 = blockRow + warp_m * 64 + i * 16 + g;
        #pragma unroll
        for (int j = 0; j < NF; j++) {
            int col = warp_n * NTW + j * 8 + t2;
            if (row0 < M) {
                __nv_bfloat162 v = __floats2bfloat162_rn(acc[i][j][0], acc[i][j][1]);
                *(__nv_bfloat162*)(C + (size_t)row0 * NT + col) = v;
            }
            if (row0 + 8 < M) {
                __nv_bfloat162 v = __floats2bfloat162_rn(acc[i][j][2], acc[i][j][3]);
                *(__nv_bfloat162*)(C + (size_t)(row0 + 8) * NT + col) = v;
            }
        }
    }
}

// ================= agg1: bf16 in, bf16 out =====================================
__global__ void agg1_kernel(const __nv_bfloat16* __restrict__ h, const int* __restrict__ rowptr,
                            const int* __restrict__ adj, const float* __restrict__ dinv,
                            const float* __restrict__ b1, __nv_bfloat16* __restrict__ h2, int n)
{
    int node = (blockIdx.x * blockDim.x + threadIdx.x) >> 5;
    int lane = threadIdx.x & 31;
    if (node >= n) return;
    int beg = rowptr[node], end = rowptr[node + 1];
    float dd = dinv[node];
    size_t l4 = (size_t)lane * 4;
    float ax = 0.f, ay = 0.f, az = 0.f, aw = 0.f;
    int e = beg;
    for (; e + 1 < end; e += 2) {
        int s0 = __ldg(adj + e), s1 = __ldg(adj + e + 1);
        float n0 = __ldg(dinv + s0) * dd, n1 = __ldg(dinv + s1) * dd;
        uint2 p0 = *(const uint2*)(h + (size_t)s0 * HIDF + l4);
        uint2 p1 = *(const uint2*)(h + (size_t)s1 * HIDF + l4);
        float2 a0 = bf2f(p0.x), b0 = bf2f(p0.y);
        float2 a1 = bf2f(p1.x), b1v = bf2f(p1.y);
        ax = fmaf(n0, a0.x, ax); ay = fmaf(n0, a0.y, ay);
        az = fmaf(n0, b0.x, az); aw = fmaf(n0, b0.y, aw);
        ax = fmaf(n1, a1.x, ax); ay = fmaf(n1, a1.y, ay);
        az = fmaf(n1, b1v.x, az); aw = fmaf(n1, b1v.y, aw);
    }
    if (e < end) {
        int s0 = __ldg(adj + e);
        float n0 = __ldg(dinv + s0) * dd;
        uint2 p0 = *(const uint2*)(h + (size_t)s0 * HIDF + l4);
        float2 a0 = bf2f(p0.x), b0 = bf2f(p0.y);
        ax = fmaf(n0, a0.x, ax); ay = fmaf(n0, a0.y, ay);
        az = fmaf(n0, b0.x, az); aw = fmaf(n0, b0.y, aw);
    }
    float d2 = dd * dd;
    uint2 ps = *(const uint2*)(h + (size_t)node * HIDF + l4);
    float2 s01 = bf2f(ps.x), s23 = bf2f(ps.y);
    float4 bv = *(const float4*)(b1 + l4);
    float tx_ = fmaf(d2, s01.x, ax) + bv.x;
    float ty_ = fmaf(d2, s01.y, ay) + bv.y;
    float tz_ = fmaf(d2, s23.x, az) + bv.z;
    float tw_ = fmaf(d2, s23.y, aw) + bv.w;
    float ox = 0.9f * fmaxf(tx_, 0.f) + 0.1f;
    float oy = 0.9f * fmaxf(ty_, 0.f) + 0.1f;
    float oz = 0.9f * fmaxf(tz_, 0.f) + 0.1f;
    float ow = 0.9f * fmaxf(tw_, 0.f) + 0.1f;
    __nv_bfloat162 o01 = __floats2bfloat162_rn(ox, oy);
    __nv_bfloat162 o23 = __floats2bfloat162_rn(oz, ow);
    uint2 st;
    st.x = *reinterpret_cast<uint32_t*>(&o01);
    st.y = *reinterpret_cast<uint32_t*>(&o23);
    *(uint2*)(h2 + (size_t)node * HIDF + l4) = st;
}

// ================= agg2: bf16 in, fp32 log-softmax out =========================
__global__ void agg2_kernel(const __nv_bfloat16* __restrict__ g, const int* __restrict__ rowptr,
                            const int* __restrict__ adj, const float* __restrict__ dinv,
                            const float* __restrict__ b2, float* __restrict__ out, int n)
{
    int node = (blockIdx.x * blockDim.x + threadIdx.x) >> 4;
    int sub  = threadIdx.x & 15;
    if (node >= n) return;
    int beg = rowptr[node], end = rowptr[node + 1];
    float dd = dinv[node];
    size_t l4 = (size_t)sub * 4;
    float ax = 0.f, ay = 0.f, az = 0.f, aw = 0.f;
    int e = beg;
    for (; e + 1 < end; e += 2) {
        int s0 = __ldg(adj + e), s1 = __ldg(adj + e + 1);
        float n0 = __ldg(dinv + s0) * dd, n1 = __ldg(dinv + s1) * dd;
        uint2 p0 = *(const uint2*)(g + (size_t)s0 * OUTF + l4);
        uint2 p1 = *(const uint2*)(g + (size_t)s1 * OUTF + l4);
        float2 a0 = bf2f(p0.x), b0 = bf2f(p0.y);
        float2 a1 = bf2f(p1.x), b1v = bf2f(p1.y);
        ax = fmaf(n0, a0.x, ax); ay = fmaf(n0, a0.y, ay);
        az = fmaf(n0, b0.x, az); aw = fmaf(n0, b0.y, aw);
        ax = fmaf(n1, a1.x, ax); ay = fmaf(n1, a1.y, ay);
        az = fmaf(n1, b1v.x, az); aw = fmaf(n1, b1v.y, aw);
    }
    if (e < end) {
        int s0 = __ldg(adj + e);
        float n0 = __ldg(dinv + s0) * dd;
        uint2 p0 = *(const uint2*)(g + (size_t)s0 * OUTF + l4);
        float2 a0 = bf2f(p0.x), b0 = bf2f(p0.y);
        ax = fmaf(n0, a0.x, ax); ay = fmaf(n0, a0.y, ay);
        az = fmaf(n0, b0.x, az); aw = fmaf(n0, b0.y, aw);
    }
    float d2 = dd * dd;
    uint2 ps = *(const uint2*)(g + (size_t)node * OUTF + l4);
    float2 s01 = bf2f(ps.x), s23 = bf2f(ps.y);
    float4 bv = *(const float4*)(b2 + l4);
    float v0 = fmaf(d2, s01.x, ax) + bv.x;
    float v1 = fmaf(d2, s01.y, ay) + bv.y;
    float v2 = fmaf(d2, s23.x, az) + bv.z;
    float v3 = fmaf(d2, s23.y, aw) + bv.w;
    float m = fmaxf(fmaxf(v0, v1), fmaxf(v2, v3));
    #pragma unroll
    for (int o = 8; o > 0; o >>= 1) m = fmaxf(m, __shfl_xor_sync(~0u, m, o, 16));
    float s = expf(v0 - m) + expf(v1 - m) + expf(v2 - m) + expf(v3 - m);
    #pragma unroll
    for (int o = 8; o > 0; o >>= 1) s += __shfl_xor_sync(~0u, s, o, 16);
    float ls = m + logf(s);
    float4 r = make_float4(v0 - ls, v1 - ls, v2 - ls, v3 - ls);
    *(float4*)(out + (size_t)node * OUTF + l4) = r;
}

// ================= launch =======================================================
extern "C" void kernel_launch(void* const* d_in, const int* in_sizes, int n_in,
                              void* d_out, int out_size)
{
    const float* x  = (const float*)d_in[0];
    const int*   ei = (const int*)  d_in[1];
    // d_in[2] edge_weight: unused (CRF softmax over singleton groups == 1.0)
    const float* W1 = (const float*)d_in[3];
    const float* b1 = (const float*)d_in[4];
    const float* W2 = (const float*)d_in[5];
    const float* b2 = (const float*)d_in[6];
    float* out = (float*)d_out;

    const int n = in_sizes[0] / INF;
    const int E = in_sizes[2];
    const int* src = ei;
    const int* dst = ei + E;

    __nv_bfloat16 *h, *h2, *g, *w1hi, *w1lo, *w2hi, *w2lo;
    float *dinv;
    int *cnt, *rowptr, *cursor, *adj, *bsum, *boff;
    cudaGetSymbolAddress((void**)&h,     g_h);
    cudaGetSymbolAddress((void**)&h2,    g_h2);
    cudaGetSymbolAddress((void**)&g,     g_g);
    cudaGetSymbolAddress((void**)&dinv,  g_dinv);
    cudaGetSymbolAddress((void**)&cnt,   g_cnt);
    cudaGetSymbolAddress((void**)&rowptr,g_rowptr);
    cudaGetSymbolAddress((void**)&cursor,g_cursor);
    cudaGetSymbolAddress((void**)&adj,   g_adj);
    cudaGetSymbolAddress((void**)&bsum,  g_bsum);
    cudaGetSymbolAddress((void**)&boff,  g_boff);
    cudaGetSymbolAddress((void**)&w1hi,  g_w1hi);
    cudaGetSymbolAddress((void**)&w1lo,  g_w1lo);
    cudaGetSymbolAddress((void**)&w2hi,  g_w2hi);
    cudaGetSymbolAddress((void**)&w2lo,  g_w2lo);

    const int nb = (n + SCAN_BS - 1) / SCAN_BS;

    constexpr int SMEM1 = 2 * (4 * HIDF * 128) + 2 * 32768 + 1024;  // split A
    constexpr int SMEM2 = 2 * (2 * OUTF * 128) + 2 * 16384 + 1024;  // bf16 A
    cudaFuncSetAttribute(mma_gemm<HIDF, 4, true>,  cudaFuncAttributeMaxDynamicSharedMemorySize, SMEM1);
    cudaFuncSetAttribute(mma_gemm<OUTF, 2, false>, cudaFuncAttributeMaxDynamicSharedMemorySize, SMEM2);

    const int mtiles = (n + 127) / 128;

    // launch order arranged so GEMM1 is the 5th launch (ncu -s 5 profiles it)
    wsplit_kernel<<<(INF*HIDF + 255)/256, 256>>>(W1, INF, HIDF, w1hi, w1lo);   // 1
    wsplit_kernel<<<(HIDF*OUTF + 255)/256, 256>>>(W2, HIDF, OUTF, w2hi, w2lo); // 2
    cudaMemsetAsync(cnt, 0, (size_t)n * sizeof(int));                          // 3
    count_kernel<<<(E + 255)/256, 256>>>(dst, E, cnt);                         // 4
    mma_gemm<HIDF, 4, true><<<mtiles, 256, SMEM1>>>(x, INF, w1hi, w1lo, h, n); // 5 (GEMM1)
    scanA_kernel<<<nb, SCAN_BS>>>(cnt, n, bsum);
    scanB_kernel<<<1, 128>>>(bsum, nb, boff, rowptr, n, E);
    scanC_kernel<<<nb, SCAN_BS>>>(cnt, boff, n, rowptr, cursor, dinv);
    fill_kernel <<<(E + 255)/256, 256>>>(src, dst, E, cursor, adj);

    // agg1: h2 = 0.9*relu(agg + dinv^2*h + b1) + 0.1   (bf16 -> bf16)
    agg1_kernel<<<((long long)n*32 + 255)/256, 256>>>(h, rowptr, adj, dinv, b1, h2, n);

    // GEMM2: g = h2 @ W2   (bf16 A, 2-term)
    mma_gemm<OUTF, 2, false><<<mtiles, 256, SMEM2>>>(h2, HIDF, w2hi, w2lo, g, n);

    // agg2: out = log_softmax(agg + dinv^2*g + b2)
    agg2_kernel<<<((long long)n*16 + 255)/256, 256>>>(g, rowptr, adj, dinv, b2, out, n);
}

// round 6
// speedup vs baseline: 2.8548x; 1.1779x over previous
#include <cuda_runtime.h>
#include <cuda_bf16.h>
#include <cstdint>

#define MAX_NODES 100000
#define MAX_EDGES 1600000
#define INF  256
#define HIDF 128
#define OUTF 64
#define SCAN_BS 1024

// ---------------- device scratch ----------------------------------------------
__device__ __align__(128) __nv_bfloat16 g_h  [(size_t)MAX_NODES * HIDF];
__device__ __align__(128) __nv_bfloat16 g_h2 [(size_t)MAX_NODES * HIDF];
__device__ __align__(128) __nv_bfloat16 g_g  [(size_t)MAX_NODES * OUTF];
__device__ __align__(128) float g_dinv[MAX_NODES];
__device__ __align__(128) int   g_cnt   [MAX_NODES];
__device__ __align__(128) int   g_rowptr[MAX_NODES + 1];
__device__ __align__(128) int   g_cursor[MAX_NODES];
__device__ __align__(128) int   g_adj   [MAX_EDGES];
__device__ __align__(128) int   g_bsum  [256];
__device__ __align__(128) int   g_boff  [256];
__device__ __align__(128) __nv_bfloat16 g_w1hi[INF * HIDF];
__device__ __align__(128) __nv_bfloat16 g_w1lo[INF * HIDF];
__device__ __align__(128) __nv_bfloat16 g_w2hi[HIDF * OUTF];
__device__ __align__(128) __nv_bfloat16 g_w2lo[HIDF * OUTF];

// ================= warp-MMA helpers =============================================
__device__ __forceinline__ uint32_t smem_u32(const void* p) {
    uint32_t a;
    asm("{ .reg .u64 t; cvta.to.shared.u64 t, %1; cvt.u32.u64 %0, t; }" : "=r"(a) : "l"(p));
    return a;
}
__device__ __forceinline__ void ldsm_x4(uint32_t* r, uint32_t addr) {
    asm volatile("ldmatrix.sync.aligned.m8n8.x4.shared.b16 {%0,%1,%2,%3}, [%4];"
                 : "=r"(r[0]), "=r"(r[1]), "=r"(r[2]), "=r"(r[3]) : "r"(addr));
}
__device__ __forceinline__ void ldsm_x2(uint32_t* r, uint32_t addr) {
    asm volatile("ldmatrix.sync.aligned.m8n8.x2.shared.b16 {%0,%1}, [%2];"
                 : "=r"(r[0]), "=r"(r[1]) : "r"(addr));
}
__device__ __forceinline__ void mma_bf16(float* d, const uint32_t* a, const uint32_t* b) {
    asm volatile(
        "mma.sync.aligned.m16n8k16.row.col.f32.bf16.bf16.f32 "
        "{%0,%1,%2,%3}, {%4,%5,%6,%7}, {%8,%9}, {%0,%1,%2,%3};"
        : "+f"(d[0]), "+f"(d[1]), "+f"(d[2]), "+f"(d[3])
        : "r"(a[0]), "r"(a[1]), "r"(a[2]), "r"(a[3]), "r"(b[0]), "r"(b[1]));
}
__device__ __forceinline__ float2 bf2f(uint32_t v) {
    return __bfloat1622float2(*reinterpret_cast<__nv_bfloat162*>(&v));
}

// ================= CSR build ====================================================
__global__ void count_kernel(const int* __restrict__ dst, int E, int* __restrict__ cnt) {
    int i = blockIdx.x * blockDim.x + threadIdx.x;
    if (i < E) atomicAdd(&cnt[dst[i]], 1);
}
__global__ void scanA_kernel(const int* __restrict__ cnt, int n, int* __restrict__ bsum) {
    int i = blockIdx.x * SCAN_BS + threadIdx.x;
    int c = (i < n) ? cnt[i] : 0;
    int lane = threadIdx.x & 31, wid = threadIdx.x >> 5;
    #pragma unroll
    for (int o = 16; o > 0; o >>= 1) c += __shfl_xor_sync(~0u, c, o);
    __shared__ int ws[32];
    if (lane == 0) ws[wid] = c;
    __syncthreads();
    if (threadIdx.x < 32) {
        int v = ws[threadIdx.x];
        #pragma unroll
        for (int o = 16; o > 0; o >>= 1) v += __shfl_xor_sync(~0u, v, o);
        if (threadIdx.x == 0) bsum[blockIdx.x] = v;
    }
}
__global__ void scanB_kernel(const int* __restrict__ bsum, int nb,
                             int* __restrict__ boff, int* __restrict__ rowptr,
                             int n, int E) {
    int t = threadIdx.x;
    int v = (t < nb) ? bsum[t] : 0;
    int lane = t & 31, w = t >> 5;
    int incl = v;
    #pragma unroll
    for (int o = 1; o < 32; o <<= 1) {
        int u = __shfl_up_sync(~0u, incl, o);
        if (lane >= o) incl += u;
    }
    __shared__ int ws[4];
    if (lane == 31) ws[w] = incl;
    __syncthreads();
    int add = 0;
    #pragma unroll
    for (int k = 0; k < 4; k++) if (k < w) add += ws[k];
    if (t < nb) boff[t] = incl - v + add;
    if (t == 0) rowptr[n] = E;
}
__global__ void scanC_kernel(const int* __restrict__ cnt, const int* __restrict__ boff,
                             int n, int* __restrict__ rowptr, int* __restrict__ cursor,
                             float* __restrict__ dinv) {
    int i = blockIdx.x * SCAN_BS + threadIdx.x;
    int c = (i < n) ? cnt[i] : 0;
    int lane = threadIdx.x & 31, wid = threadIdx.x >> 5;
    int v = c;
    #pragma unroll
    for (int o = 1; o < 32; o <<= 1) {
        int t = __shfl_up_sync(~0u, v, o);
        if (lane >= o) v += t;
    }
    __shared__ int ws[32];
    if (lane == 31) ws[wid] = v;
    __syncthreads();
    if (threadIdx.x < 32) {
        int w = ws[threadIdx.x];
        #pragma unroll
        for (int o = 1; o < 32; o <<= 1) {
            int t = __shfl_up_sync(~0u, w, o);
            if ((int)threadIdx.x >= o) w += t;
        }
        ws[threadIdx.x] = w;
    }
    __syncthreads();
    int excl = v - c + (wid > 0 ? ws[wid - 1] : 0) + boff[blockIdx.x];
    if (i < n) {
        rowptr[i] = excl;
        cursor[i] = excl;
        dinv[i] = rsqrtf((float)c + 1.0f);
    }
}
__global__ void fill_kernel(const int* __restrict__ src, const int* __restrict__ dst,
                            int E, int* __restrict__ cursor, int* __restrict__ adj) {
    int i = blockIdx.x * blockDim.x + threadIdx.x;
    if (i < E) {
        int pos = atomicAdd(&cursor[dst[i]], 1);
        adj[pos] = src[i];
    }
}

// ================= weight prep ==================================================
__global__ void wsplit_kernel(const float* __restrict__ W, int K, int N,
                              __nv_bfloat16* __restrict__ hi, __nv_bfloat16* __restrict__ lo) {
    int idx = blockIdx.x * blockDim.x + threadIdx.x;
    if (idx >= K * N) return;
    int k = idx / N, n = idx % N;
    float w = W[(size_t)k * N + n];
    __nv_bfloat16 h = __float2bfloat16(w);
    __nv_bfloat16 l = __float2bfloat16(w - __bfloat162float(h));
    int c = k >> 6, kk = k & 63;
    uint32_t off = (uint32_t)(n * 128 + kk * 2);
    uint32_t sw = off ^ ((off >> 3) & 0x70);
    size_t pos = ((size_t)c * N * 128 + sw) / 2;
    hi[pos] = h;
    lo[pos] = l;
}

// ================= persistent warp-MMA GEMM =====================================
// C[M,NT](bf16) = A[M,KCH*64] @ Wimg^T.   2-term: a_hi·(W_hi + W_lo).
// AMODE 0: A fp32 in gmem -> convert to bf16 on load. AMODE 1: A bf16 in gmem.
// grid = 148 persistent CTAs; weight image loaded to SMEM once per CTA.
template<int NT, int KCH, int AMODE>
__global__ __launch_bounds__(256, 1)
void mma_gemm(const void* __restrict__ Ain, int lda,
              const __nv_bfloat16* __restrict__ imgHi, const __nv_bfloat16* __restrict__ imgLo,
              __nv_bfloat16* __restrict__ C, int M, int ntiles)
{
    constexpr int BCH = NT * 128;
    constexpr int BB  = KCH * BCH;
    constexpr int OFF_BHI = 0;
    constexpr int OFF_BLO = BB;
    constexpr int OFF_A   = 2 * BB;
    constexpr int ASTG = 16384;          // A stage: 128 rows x 64 k x bf16
    constexpr int NTW = NT / 4;
    constexpr int NF  = NTW / 8;

    extern __shared__ char smraw[];
    char* sp = (char*)((((uintptr_t)smraw) + 1023) & ~(uintptr_t)1023);
    const uint32_t sb = smem_u32(sp);

    const int tid = threadIdx.x;
    const int wid = tid >> 5;
    const int l   = tid & 31;
    const int warp_m = wid & 1;
    const int warp_n = wid >> 1;

    // weight image -> SMEM once
    {
        const uint4* shi = (const uint4*)imgHi;
        const uint4* slo = (const uint4*)imgLo;
        uint4* dhi = (uint4*)(sp + OFF_BHI);
        uint4* dlo = (uint4*)(sp + OFF_BLO);
        for (int i = tid; i < BB / 16; i += 256) { dhi[i] = shi[i]; dlo[i] = slo[i]; }
    }

    const uint32_t xorm = (uint32_t)(l & 7) << 4;
    const uint32_t aRow = warp_m * 64 + (l & 15);
    const uint32_t aK8  = (uint32_t)(l >> 4) * 8;
    const uint32_t bN   = warp_n * NTW + (l & 7);
    const uint32_t bK8  = (uint32_t)((l >> 3) & 1) * 8;
    const uint32_t bHi0 = sb + OFF_BHI + bN * 128;
    const uint32_t bLo0 = sb + OFF_BLO + bN * 128;

    const float* Af = (const float*)Ain;
    const __nv_bfloat16* Ab = (const __nv_bfloat16*)Ain;
    const int g = l >> 2;
    const int t2 = (l & 3) * 2;

    for (int tile = blockIdx.x; tile < ntiles; tile += gridDim.x) {
        const int blockRow = tile * 128;

        float acc[4][NF][4];
        #pragma unroll
        for (int i = 0; i < 4; i++)
            #pragma unroll
            for (int j = 0; j < NF; j++)
                #pragma unroll
                for (int q = 0; q < 4; q++) acc[i][j][q] = 0.f;

        float4 pf[8];
        uint4  pb[4];
        if (AMODE == 0) {
            #pragma unroll
            for (int v = 0; v < 8; v++) {
                int vid = tid + v * 256;
                int grow = blockRow + (vid >> 4);
                pf[v] = make_float4(0.f, 0.f, 0.f, 0.f);
                if (grow < M) pf[v] = *(const float4*)(Af + (size_t)grow * lda + (vid & 15) * 4);
            }
        } else {
            #pragma unroll
            for (int v = 0; v < 4; v++) {
                int vid = tid + v * 256;
                int grow = blockRow + (vid >> 3);
                pb[v] = make_uint4(0, 0, 0, 0);
                if (grow < M) pb[v] = *(const uint4*)(Ab + (size_t)grow * lda + (vid & 7) * 8);
            }
        }

        for (int c = 0; c < KCH; c++) {
            const int buf = c & 1;
            char* aBase = sp + OFF_A + buf * ASTG;

            if (AMODE == 0) {
                #pragma unroll
                for (int v = 0; v < 8; v++) {
                    int vid = tid + v * 256;
                    int row = vid >> 4;
                    int kq  = vid & 15;
                    float4 xv = pf[v];
                    __nv_bfloat162 p01 = __floats2bfloat162_rn(xv.x, xv.y);
                    __nv_bfloat162 p23 = __floats2bfloat162_rn(xv.z, xv.w);
                    uint32_t off = (uint32_t)(row * 128 + kq * 8);
                    uint32_t sw = off ^ ((off >> 3) & 0x70);
                    *(uint2*)(aBase + sw) = make_uint2(*reinterpret_cast<uint32_t*>(&p01),
                                                       *reinterpret_cast<uint32_t*>(&p23));
                }
            } else {
                #pragma unroll
                for (int v = 0; v < 4; v++) {
                    int vid = tid + v * 256;
                    int row = vid >> 3;
                    int q   = vid & 7;
                    uint32_t off = (uint32_t)(row * 128 + q * 16);
                    uint32_t sw = off ^ ((off >> 3) & 0x70);
                    *(uint4*)(aBase + sw) = pb[v];
                }
            }
            __syncthreads();

            if (c + 1 < KCH) {
                if (AMODE == 0) {
                    #pragma unroll
                    for (int v = 0; v < 8; v++) {
                        int vid = tid + v * 256;
                        int grow = blockRow + (vid >> 4);
                        pf[v] = make_float4(0.f, 0.f, 0.f, 0.f);
                        if (grow < M)
                            pf[v] = *(const float4*)(Af + (size_t)grow * lda + (c + 1) * 64 + (vid & 15) * 4);
                    }
                } else {
                    #pragma unroll
                    for (int v = 0; v < 4; v++) {
                        int vid = tid + v * 256;
                        int grow = blockRow + (vid >> 3);
                        pb[v] = make_uint4(0, 0, 0, 0);
                        if (grow < M)
                            pb[v] = *(const uint4*)(Ab + (size_t)grow * lda + (c + 1) * 64 + (vid & 7) * 8);
                    }
                }
            }

            const uint32_t aB = sb + OFF_A + buf * ASTG + aRow * 128;
            const uint32_t bHiBase = bHi0 + c * BCH;
            const uint32_t bLoBase = bLo0 + c * BCH;
            #pragma unroll
            for (int s = 0; s < 4; s++) {
                const uint32_t akOff = ((uint32_t)(s * 16 + aK8) * 2) ^ xorm;
                const uint32_t bkOff = ((uint32_t)(s * 16 + bK8) * 2) ^ xorm;
                uint32_t bh[NF][2], bl[NF][2];
                #pragma unroll
                for (int j = 0; j < NF; j++) {
                    ldsm_x2(bh[j], bHiBase + j * 1024 + bkOff);
                    ldsm_x2(bl[j], bLoBase + j * 1024 + bkOff);
                }
                #pragma unroll
                for (int i = 0; i < 4; i++) {
                    uint32_t ah[4];
                    ldsm_x4(ah, aB + i * 2048 + akOff);
                    #pragma unroll
                    for (int j = 0; j < NF; j++) {
                        mma_bf16(acc[i][j], ah, bh[j]);
                        mma_bf16(acc[i][j], ah, bl[j]);
                    }
                }
            }
            __syncthreads();
        }

        #pragma unroll
        for (int i = 0; i < 4; i++) {
            int row0 = blockRow + warp_m * 64 + i * 16 + g;
            #pragma unroll
            for (int j = 0; j < NF; j++) {
                int col = warp_n * NTW + j * 8 + t2;
                if (row0 < M) {
                    __nv_bfloat162 v = __floats2bfloat162_rn(acc[i][j][0], acc[i][j][1]);
                    *(__nv_bfloat162*)(C + (size_t)row0 * NT + col) = v;
                }
                if (row0 + 8 < M) {
                    __nv_bfloat162 v = __floats2bfloat162_rn(acc[i][j][2], acc[i][j][3]);
                    *(__nv_bfloat162*)(C + (size_t)(row0 + 8) * NT + col) = v;
                }
            }
        }
    }
}

// ================= agg1: bf16 in, bf16 out =====================================
__global__ void agg1_kernel(const __nv_bfloat16* __restrict__ h, const int* __restrict__ rowptr,
                            const int* __restrict__ adj, const float* __restrict__ dinv,
                            const float* __restrict__ b1, __nv_bfloat16* __restrict__ h2, int n)
{
    int node = (blockIdx.x * blockDim.x + threadIdx.x) >> 5;
    int lane = threadIdx.x & 31;
    if (node >= n) return;
    int beg = rowptr[node], end = rowptr[node + 1];
    float dd = dinv[node];
    size_t l4 = (size_t)lane * 4;
    float ax = 0.f, ay = 0.f, az = 0.f, aw = 0.f;
    int e = beg;
    for (; e + 1 < end; e += 2) {
        int s0 = __ldg(adj + e), s1 = __ldg(adj + e + 1);
        float n0 = __ldg(dinv + s0) * dd, n1 = __ldg(dinv + s1) * dd;
        uint2 p0 = *(const uint2*)(h + (size_t)s0 * HIDF + l4);
        uint2 p1 = *(const uint2*)(h + (size_t)s1 * HIDF + l4);
        float2 a0 = bf2f(p0.x), b0 = bf2f(p0.y);
        float2 a1 = bf2f(p1.x), b1v = bf2f(p1.y);
        ax = fmaf(n0, a0.x, ax); ay = fmaf(n0, a0.y, ay);
        az = fmaf(n0, b0.x, az); aw = fmaf(n0, b0.y, aw);
        ax = fmaf(n1, a1.x, ax); ay = fmaf(n1, a1.y, ay);
        az = fmaf(n1, b1v.x, az); aw = fmaf(n1, b1v.y, aw);
    }
    if (e < end) {
        int s0 = __ldg(adj + e);
        float n0 = __ldg(dinv + s0) * dd;
        uint2 p0 = *(const uint2*)(h + (size_t)s0 * HIDF + l4);
        float2 a0 = bf2f(p0.x), b0 = bf2f(p0.y);
        ax = fmaf(n0, a0.x, ax); ay = fmaf(n0, a0.y, ay);
        az = fmaf(n0, b0.x, az); aw = fmaf(n0, b0.y, aw);
    }
    float d2 = dd * dd;
    uint2 ps = *(const uint2*)(h + (size_t)node * HIDF + l4);
    float2 s01 = bf2f(ps.x), s23 = bf2f(ps.y);
    float4 bv = *(const float4*)(b1 + l4);
    float tx_ = fmaf(d2, s01.x, ax) + bv.x;
    float ty_ = fmaf(d2, s01.y, ay) + bv.y;
    float tz_ = fmaf(d2, s23.x, az) + bv.z;
    float tw_ = fmaf(d2, s23.y, aw) + bv.w;
    float ox = 0.9f * fmaxf(tx_, 0.f) + 0.1f;
    float oy = 0.9f * fmaxf(ty_, 0.f) + 0.1f;
    float oz = 0.9f * fmaxf(tz_, 0.f) + 0.1f;
    float ow = 0.9f * fmaxf(tw_, 0.f) + 0.1f;
    __nv_bfloat162 o01 = __floats2bfloat162_rn(ox, oy);
    __nv_bfloat162 o23 = __floats2bfloat162_rn(oz, ow);
    uint2 st;
    st.x = *reinterpret_cast<uint32_t*>(&o01);
    st.y = *reinterpret_cast<uint32_t*>(&o23);
    *(uint2*)(h2 + (size_t)node * HIDF + l4) = st;
}

// ================= agg2: bf16 in, fp32 log-softmax out =========================
__global__ void agg2_kernel(const __nv_bfloat16* __restrict__ g, const int* __restrict__ rowptr,
                            const int* __restrict__ adj, const float* __restrict__ dinv,
                            const float* __restrict__ b2, float* __restrict__ out, int n)
{
    int node = (blockIdx.x * blockDim.x + threadIdx.x) >> 4;
    int sub  = threadIdx.x & 15;
    if (node >= n) return;
    int beg = rowptr[node], end = rowptr[node + 1];
    float dd = dinv[node];
    size_t l4 = (size_t)sub * 4;
    float ax = 0.f, ay = 0.f, az = 0.f, aw = 0.f;
    int e = beg;
    for (; e + 1 < end; e += 2) {
        int s0 = __ldg(adj + e), s1 = __ldg(adj + e + 1);
        float n0 = __ldg(dinv + s0) * dd, n1 = __ldg(dinv + s1) * dd;
        uint2 p0 = *(const uint2*)(g + (size_t)s0 * OUTF + l4);
        uint2 p1 = *(const uint2*)(g + (size_t)s1 * OUTF + l4);
        float2 a0 = bf2f(p0.x), b0 = bf2f(p0.y);
        float2 a1 = bf2f(p1.x), b1v = bf2f(p1.y);
        ax = fmaf(n0, a0.x, ax); ay = fmaf(n0, a0.y, ay);
        az = fmaf(n0, b0.x, az); aw = fmaf(n0, b0.y, aw);
        ax = fmaf(n1, a1.x, ax); ay = fmaf(n1, a1.y, ay);
        az = fmaf(n1, b1v.x, az); aw = fmaf(n1, b1v.y, aw);
    }
    if (e < end) {
        int s0 = __ldg(adj + e);
        float n0 = __ldg(dinv + s0) * dd;
        uint2 p0 = *(const uint2*)(g + (size_t)s0 * OUTF + l4);
        float2 a0 = bf2f(p0.x), b0 = bf2f(p0.y);
        ax = fmaf(n0, a0.x, ax); ay = fmaf(n0, a0.y, ay);
        az = fmaf(n0, b0.x, az); aw = fmaf(n0, b0.y, aw);
    }
    float d2 = dd * dd;
    uint2 ps = *(const uint2*)(g + (size_t)node * OUTF + l4);
    float2 s01 = bf2f(ps.x), s23 = bf2f(ps.y);
    float4 bv = *(const float4*)(b2 + l4);
    float v0 = fmaf(d2, s01.x, ax) + bv.x;
    float v1 = fmaf(d2, s01.y, ay) + bv.y;
    float v2 = fmaf(d2, s23.x, az) + bv.z;
    float v3 = fmaf(d2, s23.y, aw) + bv.w;
    float m = fmaxf(fmaxf(v0, v1), fmaxf(v2, v3));
    #pragma unroll
    for (int o = 8; o > 0; o >>= 1) m = fmaxf(m, __shfl_xor_sync(~0u, m, o, 16));
    float s = expf(v0 - m) + expf(v1 - m) + expf(v2 - m) + expf(v3 - m);
    #pragma unroll
    for (int o = 8; o > 0; o >>= 1) s += __shfl_xor_sync(~0u, s, o, 16);
    float ls = m + logf(s);
    float4 r = make_float4(v0 - ls, v1 - ls, v2 - ls, v3 - ls);
    *(float4*)(out + (size_t)node * OUTF + l4) = r;
}

// ================= launch =======================================================
extern "C" void kernel_launch(void* const* d_in, const int* in_sizes, int n_in,
                              void* d_out, int out_size)
{
    const float* x  = (const float*)d_in[0];
    const int*   ei = (const int*)  d_in[1];
    // d_in[2] edge_weight: unused (CRF softmax over singleton groups == 1.0)
    const float* W1 = (const float*)d_in[3];
    const float* b1 = (const float*)d_in[4];
    const float* W2 = (const float*)d_in[5];
    const float* b2 = (const float*)d_in[6];
    float* out = (float*)d_out;

    const int n = in_sizes[0] / INF;
    const int E = in_sizes[2];
    const int* src = ei;
    const int* dst = ei + E;

    __nv_bfloat16 *h, *h2, *g, *w1hi, *w1lo, *w2hi, *w2lo;
    float *dinv;
    int *cnt, *rowptr, *cursor, *adj, *bsum, *boff;
    cudaGetSymbolAddress((void**)&h,     g_h);
    cudaGetSymbolAddress((void**)&h2,    g_h2);
    cudaGetSymbolAddress((void**)&g,     g_g);
    cudaGetSymbolAddress((void**)&dinv,  g_dinv);
    cudaGetSymbolAddress((void**)&cnt,   g_cnt);
    cudaGetSymbolAddress((void**)&rowptr,g_rowptr);
    cudaGetSymbolAddress((void**)&cursor,g_cursor);
    cudaGetSymbolAddress((void**)&adj,   g_adj);
    cudaGetSymbolAddress((void**)&bsum,  g_bsum);
    cudaGetSymbolAddress((void**)&boff,  g_boff);
    cudaGetSymbolAddress((void**)&w1hi,  g_w1hi);
    cudaGetSymbolAddress((void**)&w1lo,  g_w1lo);
    cudaGetSymbolAddress((void**)&w2hi,  g_w2hi);
    cudaGetSymbolAddress((void**)&w2lo,  g_w2lo);

    const int nb = (n + SCAN_BS - 1) / SCAN_BS;
    const int mtiles = (n + 127) / 128;

    constexpr int SMEM1 = 2 * (4 * HIDF * 128) + 2 * 16384 + 1024;  // 128K wts + 32K A + pad
    constexpr int SMEM2 = 2 * (2 * OUTF * 128) + 2 * 16384 + 1024;  //  32K wts + 32K A + pad
    cudaFuncSetAttribute(mma_gemm<HIDF, 4, 0>, cudaFuncAttributeMaxDynamicSharedMemorySize, SMEM1);
    cudaFuncSetAttribute(mma_gemm<OUTF, 2, 1>, cudaFuncAttributeMaxDynamicSharedMemorySize, SMEM2);

    // launch order: GEMM1 is the 5th launch (ncu -s 5)
    wsplit_kernel<<<(INF*HIDF + 255)/256, 256>>>(W1, INF, HIDF, w1hi, w1lo);   // 1
    wsplit_kernel<<<(HIDF*OUTF + 255)/256, 256>>>(W2, HIDF, OUTF, w2hi, w2lo); // 2
    cudaMemsetAsync(cnt, 0, (size_t)n * sizeof(int));                          // 3
    count_kernel<<<(E + 255)/256, 256>>>(dst, E, cnt);                         // 4
    mma_gemm<HIDF, 4, 0><<<148, 256, SMEM1>>>(x, INF, w1hi, w1lo, h, n, mtiles); // 5
    scanA_kernel<<<nb, SCAN_BS>>>(cnt, n, bsum);
    scanB_kernel<<<1, 128>>>(bsum, nb, boff, rowptr, n, E);
    scanC_kernel<<<nb, SCAN_BS>>>(cnt, boff, n, rowptr, cursor, dinv);
    fill_kernel <<<(E + 255)/256, 256>>>(src, dst, E, cursor, adj);

    agg1_kernel<<<((long long)n*32 + 255)/256, 256>>>(h, rowptr, adj, dinv, b1, h2, n);

    mma_gemm<OUTF, 2, 1><<<148, 256, SMEM2>>>(h2, HIDF, w2hi, w2lo, g, n, mtiles);

    agg2_kernel<<<((long long)n*16 + 255)/256, 256>>>(g, rowptr, adj, dinv, b2, out, n);
}

// round 7
// speedup vs baseline: 2.9477x; 1.0325x over previous
#include <cuda_runtime.h>
#include <cuda_bf16.h>
#include <cstdint>

#define MAX_NODES 100000
#define MAX_EDGES 1600000
#define INF  256
#define HIDF 128
#define OUTF 64
#define SCAN_BS 1024

// ---------------- device scratch ----------------------------------------------
__device__ __align__(128) __nv_bfloat16 g_h  [(size_t)MAX_NODES * HIDF];
__device__ __align__(128) __nv_bfloat16 g_h2 [(size_t)MAX_NODES * HIDF];
__device__ __align__(128) __nv_bfloat16 g_g  [(size_t)MAX_NODES * OUTF];
__device__ __align__(128) float g_dinv[MAX_NODES];
__device__ __align__(128) int   g_cnt   [MAX_NODES];
__device__ __align__(128) int   g_rowptr[MAX_NODES + 1];
__device__ __align__(128) int   g_cursor[MAX_NODES];
__device__ __align__(128) int   g_adj   [MAX_EDGES];
__device__ __align__(128) int   g_bsum  [256];
__device__ __align__(128) int   g_boff  [256];
__device__ __align__(128) float g_w1t [INF * HIDF];          // W1 tf32 image (fp32)
__device__ __align__(128) __nv_bfloat16 g_w2hi[HIDF * OUTF]; // W2 bf16 hi
__device__ __align__(128) __nv_bfloat16 g_w2lo[HIDF * OUTF]; // W2 bf16 lo

// ================= helpers ======================================================
__device__ __forceinline__ uint32_t smem_u32(const void* p) {
    uint32_t a;
    asm("{ .reg .u64 t; cvta.to.shared.u64 t, %1; cvt.u32.u64 %0, t; }" : "=r"(a) : "l"(p));
    return a;
}
__device__ __forceinline__ void ldsm_x4(uint32_t* r, uint32_t addr) {
    asm volatile("ldmatrix.sync.aligned.m8n8.x4.shared.b16 {%0,%1,%2,%3}, [%4];"
                 : "=r"(r[0]), "=r"(r[1]), "=r"(r[2]), "=r"(r[3]) : "r"(addr));
}
__device__ __forceinline__ void ldsm_x2(uint32_t* r, uint32_t addr) {
    asm volatile("ldmatrix.sync.aligned.m8n8.x2.shared.b16 {%0,%1}, [%2];"
                 : "=r"(r[0]), "=r"(r[1]) : "r"(addr));
}
__device__ __forceinline__ void mma_bf16(float* d, const uint32_t* a, const uint32_t* b) {
    asm volatile(
        "mma.sync.aligned.m16n8k16.row.col.f32.bf16.bf16.f32 "
        "{%0,%1,%2,%3}, {%4,%5,%6,%7}, {%8,%9}, {%0,%1,%2,%3};"
        : "+f"(d[0]), "+f"(d[1]), "+f"(d[2]), "+f"(d[3])
        : "r"(a[0]), "r"(a[1]), "r"(a[2]), "r"(a[3]), "r"(b[0]), "r"(b[1]));
}
__device__ __forceinline__ void mma_tf32(float* d, const uint32_t* a, const uint32_t* b) {
    asm volatile(
        "mma.sync.aligned.m16n8k8.row.col.f32.tf32.tf32.f32 "
        "{%0,%1,%2,%3}, {%4,%5,%6,%7}, {%8,%9}, {%0,%1,%2,%3};"
        : "+f"(d[0]), "+f"(d[1]), "+f"(d[2]), "+f"(d[3])
        : "r"(a[0]), "r"(a[1]), "r"(a[2]), "r"(a[3]), "r"(b[0]), "r"(b[1]));
}
__device__ __forceinline__ void cp16(uint32_t dst, const void* src, bool valid) {
    int sz = valid ? 16 : 0;
    asm volatile("cp.async.cg.shared.global [%0], [%1], 16, %2;"
                 :: "r"(dst), "l"(src), "r"(sz) : "memory");
}
#define CP_COMMIT() asm volatile("cp.async.commit_group;" ::: "memory")
#define CP_WAIT(n)  asm volatile("cp.async.wait_group %0;" :: "n"(n) : "memory")
__device__ __forceinline__ float2 bf2f(uint32_t v) {
    return __bfloat1622float2(*reinterpret_cast<__nv_bfloat162*>(&v));
}

// ================= CSR build ====================================================
__global__ void count_kernel(const int* __restrict__ dst, int E, int* __restrict__ cnt) {
    int i = blockIdx.x * blockDim.x + threadIdx.x;
    if (i < E) atomicAdd(&cnt[dst[i]], 1);
}
__global__ void scanA_kernel(const int* __restrict__ cnt, int n, int* __restrict__ bsum) {
    int i = blockIdx.x * SCAN_BS + threadIdx.x;
    int c = (i < n) ? cnt[i] : 0;
    int lane = threadIdx.x & 31, wid = threadIdx.x >> 5;
    #pragma unroll
    for (int o = 16; o > 0; o >>= 1) c += __shfl_xor_sync(~0u, c, o);
    __shared__ int ws[32];
    if (lane == 0) ws[wid] = c;
    __syncthreads();
    if (threadIdx.x < 32) {
        int v = ws[threadIdx.x];
        #pragma unroll
        for (int o = 16; o > 0; o >>= 1) v += __shfl_xor_sync(~0u, v, o);
        if (threadIdx.x == 0) bsum[blockIdx.x] = v;
    }
}
__global__ void scanB_kernel(const int* __restrict__ bsum, int nb,
                             int* __restrict__ boff, int* __restrict__ rowptr,
                             int n, int E) {
    int t = threadIdx.x;
    int v = (t < nb) ? bsum[t] : 0;
    int lane = t & 31, w = t >> 5;
    int incl = v;
    #pragma unroll
    for (int o = 1; o < 32; o <<= 1) {
        int u = __shfl_up_sync(~0u, incl, o);
        if (lane >= o) incl += u;
    }
    __shared__ int ws[4];
    if (lane == 31) ws[w] = incl;
    __syncthreads();
    int add = 0;
    #pragma unroll
    for (int k = 0; k < 4; k++) if (k < w) add += ws[k];
    if (t < nb) boff[t] = incl - v + add;
    if (t == 0) rowptr[n] = E;
}
__global__ void scanC_kernel(const int* __restrict__ cnt, const int* __restrict__ boff,
                             int n, int* __restrict__ rowptr, int* __restrict__ cursor,
                             float* __restrict__ dinv) {
    int i = blockIdx.x * SCAN_BS + threadIdx.x;
    int c = (i < n) ? cnt[i] : 0;
    int lane = threadIdx.x & 31, wid = threadIdx.x >> 5;
    int v = c;
    #pragma unroll
    for (int o = 1; o < 32; o <<= 1) {
        int t = __shfl_up_sync(~0u, v, o);
        if (lane >= o) v += t;
    }
    __shared__ int ws[32];
    if (lane == 31) ws[wid] = v;
    __syncthreads();
    if (threadIdx.x < 32) {
        int w = ws[threadIdx.x];
        #pragma unroll
        for (int o = 1; o < 32; o <<= 1) {
            int t = __shfl_up_sync(~0u, w, o);
            if ((int)threadIdx.x >= o) w += t;
        }
        ws[threadIdx.x] = w;
    }
    __syncthreads();
    int excl = v - c + (wid > 0 ? ws[wid - 1] : 0) + boff[blockIdx.x];
    if (i < n) {
        rowptr[i] = excl;
        cursor[i] = excl;
        dinv[i] = rsqrtf((float)c + 1.0f);
    }
}
__global__ void fill_kernel(const int* __restrict__ src, const int* __restrict__ dst,
                            int E, int* __restrict__ cursor, int* __restrict__ adj) {
    int i = blockIdx.x * blockDim.x + threadIdx.x;
    if (i < E) {
        int pos = atomicAdd(&cursor[dst[i]], 1);
        adj[pos] = src[i];
    }
}

// ================= weight prep ==================================================
// W1 -> tf32(fp32) image: chunk c=k/64, row n (256B), swizzled in 16B units
__global__ void wtf32_kernel(const float* __restrict__ W, int K, int N,
                             float* __restrict__ img) {
    int idx = blockIdx.x * blockDim.x + threadIdx.x;
    if (idx >= K * N) return;
    int k = idx / N, n = idx % N;
    int c = k >> 6, kk = k & 63;
    uint32_t off = (uint32_t)(n * 256 + kk * 4);
    uint32_t sw = off ^ (((off >> 8) & 7) << 4);
    img[((size_t)c * N * 256 + sw) / 4] = W[(size_t)k * N + n];
}
// W2 -> bf16 hi/lo image: chunk c=k/64, row n (128B), SW128
__global__ void wsplit_kernel(const float* __restrict__ W, int K, int N,
                              __nv_bfloat16* __restrict__ hi, __nv_bfloat16* __restrict__ lo) {
    int idx = blockIdx.x * blockDim.x + threadIdx.x;
    if (idx >= K * N) return;
    int k = idx / N, n = idx % N;
    float w = W[(size_t)k * N + n];
    __nv_bfloat16 h = __float2bfloat16(w);
    __nv_bfloat16 l = __float2bfloat16(w - __bfloat162float(h));
    int c = k >> 6, kk = k & 63;
    uint32_t off = (uint32_t)(n * 128 + kk * 2);
    uint32_t sw = off ^ ((off >> 3) & 0x70);
    size_t pos = ((size_t)c * N * 128 + sw) / 2;
    hi[pos] = h;
    lo[pos] = l;
}

// ================= GEMM1: persistent tf32, cp.async ===========================
// C[M,128](bf16) = A[M,256](fp32) @ W1^T, single-pass tf32.
__global__ __launch_bounds__(256, 1)
void tf32_gemm(const float* __restrict__ A, int lda, const float* __restrict__ img,
               __nv_bfloat16* __restrict__ C, int M, int ntiles)
{
    constexpr int NT  = HIDF;       // 128
    constexpr int KCH = 4;
    constexpr int BCH = NT * 256;   // 32KB weight chunk
    constexpr int BB  = KCH * BCH;  // 128KB
    constexpr int OFF_A = BB;
    constexpr int ASTG = 32768;     // 128 rows x 256B
    constexpr int NTW = NT / 4;     // 32
    constexpr int NF  = NTW / 8;    // 4

    extern __shared__ char smraw[];
    char* sp = (char*)((((uintptr_t)smraw) + 1023) & ~(uintptr_t)1023);
    const uint32_t sb = smem_u32(sp);
    const uint32_t sbA = sb + OFF_A;

    const int tid = threadIdx.x;
    const int wid = tid >> 5;
    const int l   = tid & 31;
    const int warp_m = wid & 1;
    const int warp_n = wid >> 1;

    // weights -> SMEM once
    {
        const uint4* s = (const uint4*)img;
        uint4* d = (uint4*)sp;
        for (int i = tid; i < BB / 16; i += 256) d[i] = s[i];
    }

    const uint32_t xorm = (uint32_t)(l & 7) << 4;
    const uint32_t aRow = warp_m * 64 + (l & 15);
    const uint32_t aK16 = (uint32_t)(l >> 4);        // 0/1
    const uint32_t bN   = warp_n * NTW + (l & 7);
    const uint32_t bK16 = (uint32_t)((l >> 3) & 1);  // 0/1
    const int g  = l >> 2;
    const int t2 = (l & 3) * 2;

    for (int tile = blockIdx.x; tile < ntiles; tile += gridDim.x) {
        const int blockRow = tile * 128;

        float acc[4][NF][4];
        #pragma unroll
        for (int i = 0; i < 4; i++)
            #pragma unroll
            for (int j = 0; j < NF; j++)
                #pragma unroll
                for (int q = 0; q < 4; q++) acc[i][j][q] = 0.f;

        // prologue: chunk 0
        #pragma unroll
        for (int v = 0; v < 8; v++) {
            int vid = tid + v * 256;
            int row = vid >> 4;
            int u   = vid & 15;
            int grow = blockRow + row;
            bool valid = grow < M;
            const float* src = A + (size_t)(valid ? grow : 0) * lda + u * 4;
            uint32_t dst = sbA + row * 256 + (((uint32_t)u * 16) ^ (((uint32_t)row & 7) << 4));
            cp16(dst, src, valid);
        }
        CP_COMMIT();

        for (int c = 0; c < KCH; c++) {
            const int buf = c & 1;
            if (c + 1 < KCH) {
                const int nb = (c + 1) & 1;
                #pragma unroll
                for (int v = 0; v < 8; v++) {
                    int vid = tid + v * 256;
                    int row = vid >> 4;
                    int u   = vid & 15;
                    int grow = blockRow + row;
                    bool valid = grow < M;
                    const float* src = A + (size_t)(valid ? grow : 0) * lda + (c + 1) * 64 + u * 4;
                    uint32_t dst = sbA + nb * ASTG + row * 256
                                 + (((uint32_t)u * 16) ^ (((uint32_t)row & 7) << 4));
                    cp16(dst, src, valid);
                }
                CP_COMMIT();
                CP_WAIT(1);
            } else {
                CP_WAIT(0);
            }
            __syncthreads();

            const uint32_t aB = sbA + buf * ASTG;
            const uint32_t bB = sb + c * BCH;
            #pragma unroll
            for (int s = 0; s < 8; s++) {
                const uint32_t koff = (((uint32_t)s * 32)) ;
                uint32_t bf[NF][2];
                #pragma unroll
                for (int j = 0; j < NF; j++)
                    ldsm_x2(bf[j], bB + (bN + j * 8) * 256 + ((koff + bK16 * 16) ^ xorm));
                #pragma unroll
                for (int i = 0; i < 4; i++) {
                    uint32_t af[4];
                    ldsm_x4(af, aB + (aRow + i * 16) * 256 + ((koff + aK16 * 16) ^ xorm));
                    #pragma unroll
                    for (int j = 0; j < NF; j++)
                        mma_tf32(acc[i][j], af, bf[j]);
                }
            }
            __syncthreads();
        }

        #pragma unroll
        for (int i = 0; i < 4; i++) {
            int row0 = blockRow + warp_m * 64 + i * 16 + g;
            #pragma unroll
            for (int j = 0; j < NF; j++) {
                int col = warp_n * NTW + j * 8 + t2;
                if (row0 < M) {
                    __nv_bfloat162 v = __floats2bfloat162_rn(acc[i][j][0], acc[i][j][1]);
                    *(__nv_bfloat162*)(C + (size_t)row0 * NT + col) = v;
                }
                if (row0 + 8 < M) {
                    __nv_bfloat162 v = __floats2bfloat162_rn(acc[i][j][2], acc[i][j][3]);
                    *(__nv_bfloat162*)(C + (size_t)(row0 + 8) * NT + col) = v;
                }
            }
        }
    }
}

// ================= GEMM2: persistent bf16 2-term, cp.async, 2 CTA/SM ===========
__global__ __launch_bounds__(256, 2)
void bf16_gemm(const __nv_bfloat16* __restrict__ A, int lda,
               const __nv_bfloat16* __restrict__ imgHi, const __nv_bfloat16* __restrict__ imgLo,
               __nv_bfloat16* __restrict__ C, int M, int ntiles)
{
    constexpr int NT  = OUTF;       // 64
    constexpr int KCH = 2;
    constexpr int BCH = NT * 128;   // 8KB per chunk per array
    constexpr int BB  = KCH * BCH;  // 16KB per array
    constexpr int OFF_BLO = BB;
    constexpr int OFF_A   = 2 * BB;
    constexpr int ASTG = 16384;
    constexpr int NTW = NT / 4;     // 16
    constexpr int NF  = NTW / 8;    // 2

    extern __shared__ char smraw[];
    char* sp = (char*)((((uintptr_t)smraw) + 1023) & ~(uintptr_t)1023);
    const uint32_t sb = smem_u32(sp);
    const uint32_t sbA = sb + OFF_A;

    const int tid = threadIdx.x;
    const int wid = tid >> 5;
    const int l   = tid & 31;
    const int warp_m = wid & 1;
    const int warp_n = wid >> 1;

    {
        const uint4* shi = (const uint4*)imgHi;
        const uint4* slo = (const uint4*)imgLo;
        uint4* dhi = (uint4*)sp;
        uint4* dlo = (uint4*)(sp + OFF_BLO);
        for (int i = tid; i < BB / 16; i += 256) { dhi[i] = shi[i]; dlo[i] = slo[i]; }
    }

    const uint32_t xorm = (uint32_t)(l & 7) << 4;
    const uint32_t aRow = warp_m * 64 + (l & 15);
    const uint32_t aK8  = (uint32_t)(l >> 4) * 8;
    const uint32_t bN   = warp_n * NTW + (l & 7);
    const uint32_t bK8  = (uint32_t)((l >> 3) & 1) * 8;
    const int g  = l >> 2;
    const int t2 = (l & 3) * 2;

    for (int tile = blockIdx.x; tile < ntiles; tile += gridDim.x) {
        const int blockRow = tile * 128;

        float acc[4][NF][4];
        #pragma unroll
        for (int i = 0; i < 4; i++)
            #pragma unroll
            for (int j = 0; j < NF; j++)
                #pragma unroll
                for (int q = 0; q < 4; q++) acc[i][j][q] = 0.f;

        #pragma unroll
        for (int v = 0; v < 4; v++) {
            int vid = tid + v * 256;
            int row = vid >> 3;
            int u   = vid & 7;
            int grow = blockRow + row;
            bool valid = grow < M;
            const __nv_bfloat16* src = A + (size_t)(valid ? grow : 0) * lda + u * 8;
            uint32_t dst = sbA + row * 128 + (((uint32_t)u * 16) ^ (((uint32_t)row & 7) << 4));
            cp16(dst, src, valid);
        }
        CP_COMMIT();

        for (int c = 0; c < KCH; c++) {
            const int buf = c & 1;
            if (c + 1 < KCH) {
                const int nb = (c + 1) & 1;
                #pragma unroll
                for (int v = 0; v < 4; v++) {
                    int vid = tid + v * 256;
                    int row = vid >> 3;
                    int u   = vid & 7;
                    int grow = blockRow + row;
                    bool valid = grow < M;
                    const __nv_bfloat16* src = A + (size_t)(valid ? grow : 0) * lda + (c + 1) * 64 + u * 8;
                    uint32_t dst = sbA + nb * ASTG + row * 128
                                 + (((uint32_t)u * 16) ^ (((uint32_t)row & 7) << 4));
                    cp16(dst, src, valid);
                }
                CP_COMMIT();
                CP_WAIT(1);
            } else {
                CP_WAIT(0);
            }
            __syncthreads();

            const uint32_t aB = sbA + buf * ASTG + aRow * 128;
            const uint32_t bHiBase = sb + c * BCH + bN * 128;
            const uint32_t bLoBase = bHiBase + OFF_BLO;
            #pragma unroll
            for (int s = 0; s < 4; s++) {
                const uint32_t akOff = ((uint32_t)(s * 16 + aK8) * 2) ^ xorm;
                const uint32_t bkOff = ((uint32_t)(s * 16 + bK8) * 2) ^ xorm;
                uint32_t bh[NF][2], bl[NF][2];
                #pragma unroll
                for (int j = 0; j < NF; j++) {
                    ldsm_x2(bh[j], bHiBase + j * 1024 + bkOff);
                    ldsm_x2(bl[j], bLoBase + j * 1024 + bkOff);
                }
                #pragma unroll
                for (int i = 0; i < 4; i++) {
                    uint32_t ah[4];
                    ldsm_x4(ah, aB + i * 2048 + akOff);
                    #pragma unroll
                    for (int j = 0; j < NF; j++) {
                        mma_bf16(acc[i][j], ah, bh[j]);
                        mma_bf16(acc[i][j], ah, bl[j]);
                    }
                }
            }
            __syncthreads();
        }

        #pragma unroll
        for (int i = 0; i < 4; i++) {
            int row0 = blockRow + warp_m * 64 + i * 16 + g;
            #pragma unroll
            for (int j = 0; j < NF; j++) {
                int col = warp_n * NTW + j * 8 + t2;
                if (row0 < M) {
                    __nv_bfloat162 v = __floats2bfloat162_rn(acc[i][j][0], acc[i][j][1]);
                    *(__nv_bfloat162*)(C + (size_t)row0 * NT + col) = v;
                }
                if (row0 + 8 < M) {
                    __nv_bfloat162 v = __floats2bfloat162_rn(acc[i][j][2], acc[i][j][3]);
                    *(__nv_bfloat162*)(C + (size_t)(row0 + 8) * NT + col) = v;
                }
            }
        }
    }
}

// ================= agg1: bf16 in, bf16 out =====================================
__global__ void agg1_kernel(const __nv_bfloat16* __restrict__ h, const int* __restrict__ rowptr,
                            const int* __restrict__ adj, const float* __restrict__ dinv,
                            const float* __restrict__ b1, __nv_bfloat16* __restrict__ h2, int n)
{
    int node = (blockIdx.x * blockDim.x + threadIdx.x) >> 5;
    int lane = threadIdx.x & 31;
    if (node >= n) return;
    int beg = rowptr[node], end = rowptr[node + 1];
    float dd = dinv[node];
    size_t l4 = (size_t)lane * 4;
    float ax = 0.f, ay = 0.f, az = 0.f, aw = 0.f;
    int e = beg;
    for (; e + 1 < end; e += 2) {
        int s0 = __ldg(adj + e), s1 = __ldg(adj + e + 1);
        float n0 = __ldg(dinv + s0) * dd, n1 = __ldg(dinv + s1) * dd;
        uint2 p0 = *(const uint2*)(h + (size_t)s0 * HIDF + l4);
        uint2 p1 = *(const uint2*)(h + (size_t)s1 * HIDF + l4);
        float2 a0 = bf2f(p0.x), b0 = bf2f(p0.y);
        float2 a1 = bf2f(p1.x), b1v = bf2f(p1.y);
        ax = fmaf(n0, a0.x, ax); ay = fmaf(n0, a0.y, ay);
        az = fmaf(n0, b0.x, az); aw = fmaf(n0, b0.y, aw);
        ax = fmaf(n1, a1.x, ax); ay = fmaf(n1, a1.y, ay);
        az = fmaf(n1, b1v.x, az); aw = fmaf(n1, b1v.y, aw);
    }
    if (e < end) {
        int s0 = __ldg(adj + e);
        float n0 = __ldg(dinv + s0) * dd;
        uint2 p0 = *(const uint2*)(h + (size_t)s0 * HIDF + l4);
        float2 a0 = bf2f(p0.x), b0 = bf2f(p0.y);
        ax = fmaf(n0, a0.x, ax); ay = fmaf(n0, a0.y, ay);
        az = fmaf(n0, b0.x, az); aw = fmaf(n0, b0.y, aw);
    }
    float d2 = dd * dd;
    uint2 ps = *(const uint2*)(h + (size_t)node * HIDF + l4);
    float2 s01 = bf2f(ps.x), s23 = bf2f(ps.y);
    float4 bv = *(const float4*)(b1 + l4);
    float tx_ = fmaf(d2, s01.x, ax) + bv.x;
    float ty_ = fmaf(d2, s01.y, ay) + bv.y;
    float tz_ = fmaf(d2, s23.x, az) + bv.z;
    float tw_ = fmaf(d2, s23.y, aw) + bv.w;
    float ox = 0.9f * fmaxf(tx_, 0.f) + 0.1f;
    float oy = 0.9f * fmaxf(ty_, 0.f) + 0.1f;
    float oz = 0.9f * fmaxf(tz_, 0.f) + 0.1f;
    float ow = 0.9f * fmaxf(tw_, 0.f) + 0.1f;
    __nv_bfloat162 o01 = __floats2bfloat162_rn(ox, oy);
    __nv_bfloat162 o23 = __floats2bfloat162_rn(oz, ow);
    uint2 st;
    st.x = *reinterpret_cast<uint32_t*>(&o01);
    st.y = *reinterpret_cast<uint32_t*>(&o23);
    *(uint2*)(h2 + (size_t)node * HIDF + l4) = st;
}

// ================= agg2: bf16 in, fp32 log-softmax out =========================
__global__ void agg2_kernel(const __nv_bfloat16* __restrict__ g, const int* __restrict__ rowptr,
                            const int* __restrict__ adj, const float* __restrict__ dinv,
                            const float* __restrict__ b2, float* __restrict__ out, int n)
{
    int node = (blockIdx.x * blockDim.x + threadIdx.x) >> 4;
    int sub  = threadIdx.x & 15;
    if (node >= n) return;
    int beg = rowptr[node], end = rowptr[node + 1];
    float dd = dinv[node];
    size_t l4 = (size_t)sub * 4;
    float ax = 0.f, ay = 0.f, az = 0.f, aw = 0.f;
    int e = beg;
    for (; e + 1 < end; e += 2) {
        int s0 = __ldg(adj + e), s1 = __ldg(adj + e + 1);
        float n0 = __ldg(dinv + s0) * dd, n1 = __ldg(dinv + s1) * dd;
        uint2 p0 = *(const uint2*)(g + (size_t)s0 * OUTF + l4);
        uint2 p1 = *(const uint2*)(g + (size_t)s1 * OUTF + l4);
        float2 a0 = bf2f(p0.x), b0 = bf2f(p0.y);
        float2 a1 = bf2f(p1.x), b1v = bf2f(p1.y);
        ax = fmaf(n0, a0.x, ax); ay = fmaf(n0, a0.y, ay);
        az = fmaf(n0, b0.x, az); aw = fmaf(n0, b0.y, aw);
        ax = fmaf(n1, a1.x, ax); ay = fmaf(n1, a1.y, ay);
        az = fmaf(n1, b1v.x, az); aw = fmaf(n1, b1v.y, aw);
    }
    if (e < end) {
        int s0 = __ldg(adj + e);
        float n0 = __ldg(dinv + s0) * dd;
        uint2 p0 = *(const uint2*)(g + (size_t)s0 * OUTF + l4);
        float2 a0 = bf2f(p0.x), b0 = bf2f(p0.y);
        ax = fmaf(n0, a0.x, ax); ay = fmaf(n0, a0.y, ay);
        az = fmaf(n0, b0.x, az); aw = fmaf(n0, b0.y, aw);
    }
    float d2 = dd * dd;
    uint2 ps = *(const uint2*)(g + (size_t)node * OUTF + l4);
    float2 s01 = bf2f(ps.x), s23 = bf2f(ps.y);
    float4 bv = *(const float4*)(b2 + l4);
    float v0 = fmaf(d2, s01.x, ax) + bv.x;
    float v1 = fmaf(d2, s01.y, ay) + bv.y;
    float v2 = fmaf(d2, s23.x, az) + bv.z;
    float v3 = fmaf(d2, s23.y, aw) + bv.w;
    float m = fmaxf(fmaxf(v0, v1), fmaxf(v2, v3));
    #pragma unroll
    for (int o = 8; o > 0; o >>= 1) m = fmaxf(m, __shfl_xor_sync(~0u, m, o, 16));
    float s = expf(v0 - m) + expf(v1 - m) + expf(v2 - m) + expf(v3 - m);
    #pragma unroll
    for (int o = 8; o > 0; o >>= 1) s += __shfl_xor_sync(~0u, s, o, 16);
    float ls = m + logf(s);
    float4 r = make_float4(v0 - ls, v1 - ls, v2 - ls, v3 - ls);
    *(float4*)(out + (size_t)node * OUTF + l4) = r;
}

// ================= launch =======================================================
extern "C" void kernel_launch(void* const* d_in, const int* in_sizes, int n_in,
                              void* d_out, int out_size)
{
    const float* x  = (const float*)d_in[0];
    const int*   ei = (const int*)  d_in[1];
    // d_in[2] edge_weight: unused (CRF softmax over singleton groups == 1.0)
    const float* W1 = (const float*)d_in[3];
    const float* b1 = (const float*)d_in[4];
    const float* W2 = (const float*)d_in[5];
    const float* b2 = (const float*)d_in[6];
    float* out = (float*)d_out;

    const int n = in_sizes[0] / INF;
    const int E = in_sizes[2];
    const int* src = ei;
    const int* dst = ei + E;

    __nv_bfloat16 *h, *h2, *g, *w2hi, *w2lo;
    float *dinv, *w1t;
    int *cnt, *rowptr, *cursor, *adj, *bsum, *boff;
    cudaGetSymbolAddress((void**)&h,     g_h);
    cudaGetSymbolAddress((void**)&h2,    g_h2);
    cudaGetSymbolAddress((void**)&g,     g_g);
    cudaGetSymbolAddress((void**)&dinv,  g_dinv);
    cudaGetSymbolAddress((void**)&cnt,   g_cnt);
    cudaGetSymbolAddress((void**)&rowptr,g_rowptr);
    cudaGetSymbolAddress((void**)&cursor,g_cursor);
    cudaGetSymbolAddress((void**)&adj,   g_adj);
    cudaGetSymbolAddress((void**)&bsum,  g_bsum);
    cudaGetSymbolAddress((void**)&boff,  g_boff);
    cudaGetSymbolAddress((void**)&w1t,   g_w1t);
    cudaGetSymbolAddress((void**)&w2hi,  g_w2hi);
    cudaGetSymbolAddress((void**)&w2lo,  g_w2lo);

    const int nb = (n + SCAN_BS - 1) / SCAN_BS;
    const int mtiles = (n + 127) / 128;

    constexpr int SMEM1 = INF * HIDF * 4 + 2 * 32768 + 1024;   // 128K wts + 64K A + pad
    constexpr int SMEM2 = 2 * (HIDF * OUTF * 2) + 2 * 16384 + 1024;
    cudaFuncSetAttribute(tf32_gemm, cudaFuncAttributeMaxDynamicSharedMemorySize, SMEM1);
    cudaFuncSetAttribute(bf16_gemm, cudaFuncAttributeMaxDynamicSharedMemorySize, SMEM2);

    // launch order: GEMM1 is the 5th launch (ncu -s 5)
    wtf32_kernel <<<(INF*HIDF + 255)/256, 256>>>(W1, INF, HIDF, w1t);          // 1
    wsplit_kernel<<<(HIDF*OUTF + 255)/256, 256>>>(W2, HIDF, OUTF, w2hi, w2lo); // 2
    cudaMemsetAsync(cnt, 0, (size_t)n * sizeof(int));                          // 3
    count_kernel<<<(E + 255)/256, 256>>>(dst, E, cnt);                         // 4
    tf32_gemm<<<148, 256, SMEM1>>>(x, INF, w1t, h, n, mtiles);                 // 5
    scanA_kernel<<<nb, SCAN_BS>>>(cnt, n, bsum);
    scanB_kernel<<<1, 128>>>(bsum, nb, boff, rowptr, n, E);
    scanC_kernel<<<nb, SCAN_BS>>>(cnt, boff, n, rowptr, cursor, dinv);
    fill_kernel <<<(E + 255)/256, 256>>>(src, dst, E, cursor, adj);

    agg1_kernel<<<((long long)n*32 + 255)/256, 256>>>(h, rowptr, adj, dinv, b1, h2, n);

    bf16_gemm<<<296, 256, SMEM2>>>(h2, HIDF, w2hi, w2lo, g, n, mtiles);

    agg2_kernel<<<((long long)n*16 + 255)/256, 256>>>(g, rowptr, adj, dinv, b2, out, n);
}

// round 8
// speedup vs baseline: 3.1216x; 1.0590x over previous
#include <cuda_runtime.h>
#include <cuda_bf16.h>
#include <cstdint>

#define MAX_NODES 100000
#define MAX_EDGES 1600000
#define INF  256
#define HIDF 128
#define OUTF 64
#define SCAN_BS 1024

// ---------------- device scratch ----------------------------------------------
__device__ __align__(128) __nv_bfloat16 g_h  [(size_t)MAX_NODES * HIDF];
__device__ __align__(128) __nv_bfloat16 g_h2 [(size_t)MAX_NODES * HIDF];
__device__ __align__(128) __nv_bfloat16 g_g  [(size_t)MAX_NODES * OUTF];
__device__ __align__(128) float g_dinv[MAX_NODES];
__device__ __align__(128) int   g_cnt   [MAX_NODES];
__device__ __align__(128) int   g_rowptr[MAX_NODES + 1];
__device__ __align__(128) int   g_cursor[MAX_NODES];
__device__ __align__(128) int   g_adj   [MAX_EDGES];
__device__ __align__(128) int   g_bsum  [256];
__device__ __align__(128) int   g_boff  [256];
__device__ __align__(128) float g_w1t [INF * HIDF];          // W1 tf32 image
__device__ __align__(128) __nv_bfloat16 g_w2hi[HIDF * OUTF];
__device__ __align__(128) __nv_bfloat16 g_w2lo[HIDF * OUTF];

// ================= helpers ======================================================
__device__ __forceinline__ uint32_t smem_u32(const void* p) {
    uint32_t a;
    asm("{ .reg .u64 t; cvta.to.shared.u64 t, %1; cvt.u32.u64 %0, t; }" : "=r"(a) : "l"(p));
    return a;
}
__device__ __forceinline__ void ldsm_x4(uint32_t* r, uint32_t addr) {
    asm volatile("ldmatrix.sync.aligned.m8n8.x4.shared.b16 {%0,%1,%2,%3}, [%4];"
                 : "=r"(r[0]), "=r"(r[1]), "=r"(r[2]), "=r"(r[3]) : "r"(addr));
}
__device__ __forceinline__ void ldsm_x2(uint32_t* r, uint32_t addr) {
    asm volatile("ldmatrix.sync.aligned.m8n8.x2.shared.b16 {%0,%1}, [%2];"
                 : "=r"(r[0]), "=r"(r[1]) : "r"(addr));
}
__device__ __forceinline__ void mma_bf16(float* d, const uint32_t* a, const uint32_t* b) {
    asm volatile(
        "mma.sync.aligned.m16n8k16.row.col.f32.bf16.bf16.f32 "
        "{%0,%1,%2,%3}, {%4,%5,%6,%7}, {%8,%9}, {%0,%1,%2,%3};"
        : "+f"(d[0]), "+f"(d[1]), "+f"(d[2]), "+f"(d[3])
        : "r"(a[0]), "r"(a[1]), "r"(a[2]), "r"(a[3]), "r"(b[0]), "r"(b[1]));
}
__device__ __forceinline__ void mma_tf32(float* d, const uint32_t* a, const uint32_t* b) {
    asm volatile(
        "mma.sync.aligned.m16n8k8.row.col.f32.tf32.tf32.f32 "
        "{%0,%1,%2,%3}, {%4,%5,%6,%7}, {%8,%9}, {%0,%1,%2,%3};"
        : "+f"(d[0]), "+f"(d[1]), "+f"(d[2]), "+f"(d[3])
        : "r"(a[0]), "r"(a[1]), "r"(a[2]), "r"(a[3]), "r"(b[0]), "r"(b[1]));
}
__device__ __forceinline__ void cp16(uint32_t dst, const void* src, bool valid) {
    int sz = valid ? 16 : 0;
    asm volatile("cp.async.cg.shared.global [%0], [%1], 16, %2;"
                 :: "r"(dst), "l"(src), "r"(sz) : "memory");
}
#define CP_COMMIT() asm volatile("cp.async.commit_group;" ::: "memory")
#define CP_WAIT(n)  asm volatile("cp.async.wait_group %0;" :: "n"(n) : "memory")
__device__ __forceinline__ float2 bf2f(uint32_t v) {
    return __bfloat1622float2(*reinterpret_cast<__nv_bfloat162*>(&v));
}

// ================= CSR build ====================================================
__global__ void count_kernel(const int* __restrict__ dst, int E, int* __restrict__ cnt) {
    int i = blockIdx.x * blockDim.x + threadIdx.x;
    if (i < E) atomicAdd(&cnt[dst[i]], 1);
}
__global__ void scanA_kernel(const int* __restrict__ cnt, int n, int* __restrict__ bsum) {
    int i = blockIdx.x * SCAN_BS + threadIdx.x;
    int c = (i < n) ? cnt[i] : 0;
    int lane = threadIdx.x & 31, wid = threadIdx.x >> 5;
    #pragma unroll
    for (int o = 16; o > 0; o >>= 1) c += __shfl_xor_sync(~0u, c, o);
    __shared__ int ws[32];
    if (lane == 0) ws[wid] = c;
    __syncthreads();
    if (threadIdx.x < 32) {
        int v = ws[threadIdx.x];
        #pragma unroll
        for (int o = 16; o > 0; o >>= 1) v += __shfl_xor_sync(~0u, v, o);
        if (threadIdx.x == 0) bsum[blockIdx.x] = v;
    }
}
__global__ void scanB_kernel(const int* __restrict__ bsum, int nb,
                             int* __restrict__ boff, int* __restrict__ rowptr,
                             int n, int E) {
    int t = threadIdx.x;
    int v = (t < nb) ? bsum[t] : 0;
    int lane = t & 31, w = t >> 5;
    int incl = v;
    #pragma unroll
    for (int o = 1; o < 32; o <<= 1) {
        int u = __shfl_up_sync(~0u, incl, o);
        if (lane >= o) incl += u;
    }
    __shared__ int ws[4];
    if (lane == 31) ws[w] = incl;
    __syncthreads();
    int add = 0;
    #pragma unroll
    for (int k = 0; k < 4; k++) if (k < w) add += ws[k];
    if (t < nb) boff[t] = incl - v + add;
    if (t == 0) rowptr[n] = E;
}
__global__ void scanC_kernel(const int* __restrict__ cnt, const int* __restrict__ boff,
                             int n, int* __restrict__ rowptr, int* __restrict__ cursor,
                             float* __restrict__ dinv) {
    int i = blockIdx.x * SCAN_BS + threadIdx.x;
    int c = (i < n) ? cnt[i] : 0;
    int lane = threadIdx.x & 31, wid = threadIdx.x >> 5;
    int v = c;
    #pragma unroll
    for (int o = 1; o < 32; o <<= 1) {
        int t = __shfl_up_sync(~0u, v, o);
        if (lane >= o) v += t;
    }
    __shared__ int ws[32];
    if (lane == 31) ws[wid] = v;
    __syncthreads();
    if (threadIdx.x < 32) {
        int w = ws[threadIdx.x];
        #pragma unroll
        for (int o = 1; o < 32; o <<= 1) {
            int t = __shfl_up_sync(~0u, w, o);
            if ((int)threadIdx.x >= o) w += t;
        }
        ws[threadIdx.x] = w;
    }
    __syncthreads();
    int excl = v - c + (wid > 0 ? ws[wid - 1] : 0) + boff[blockIdx.x];
    if (i < n) {
        rowptr[i] = excl;
        cursor[i] = excl;
        dinv[i] = rsqrtf((float)c + 1.0f);
    }
}
__global__ void fill_kernel(const int* __restrict__ src, const int* __restrict__ dst,
                            int E, int* __restrict__ cursor, int* __restrict__ adj) {
    int i = blockIdx.x * blockDim.x + threadIdx.x;
    if (i < E) {
        int pos = atomicAdd(&cursor[dst[i]], 1);
        adj[pos] = src[i];
    }
}

// ================= weight prep ==================================================
__global__ void wtf32_kernel(const float* __restrict__ W, int K, int N,
                             float* __restrict__ img) {
    int idx = blockIdx.x * blockDim.x + threadIdx.x;
    if (idx >= K * N) return;
    int k = idx / N, n = idx % N;
    int c = k >> 6, kk = k & 63;
    uint32_t off = (uint32_t)(n * 256 + kk * 4);
    uint32_t sw = off ^ (((off >> 8) & 7) << 4);
    img[((size_t)c * N * 256 + sw) / 4] = W[(size_t)k * N + n];
}
__global__ void wsplit_kernel(const float* __restrict__ W, int K, int N,
                              __nv_bfloat16* __restrict__ hi, __nv_bfloat16* __restrict__ lo) {
    int idx = blockIdx.x * blockDim.x + threadIdx.x;
    if (idx >= K * N) return;
    int k = idx / N, n = idx % N;
    float w = W[(size_t)k * N + n];
    __nv_bfloat16 h = __float2bfloat16(w);
    __nv_bfloat16 l = __float2bfloat16(w - __bfloat162float(h));
    int c = k >> 6, kk = k & 63;
    uint32_t off = (uint32_t)(n * 128 + kk * 2);
    uint32_t sw = off ^ ((off >> 3) & 0x70);
    size_t pos = ((size_t)c * N * 128 + sw) / 2;
    hi[pos] = h;
    lo[pos] = l;
}

// ================= GEMM1: persistent tf32, 512 threads, cp.async ==============
__global__ __launch_bounds__(512, 1)
void tf32_gemm(const float* __restrict__ A, int lda, const float* __restrict__ img,
               __nv_bfloat16* __restrict__ C, int M, int ntiles)
{
    constexpr int NT  = HIDF;
    constexpr int KCH = 4;
    constexpr int BCH = NT * 256;
    constexpr int BB  = KCH * BCH;
    constexpr int OFF_A = BB;
    constexpr int ASTG = 32768;
    constexpr int NF  = 4;           // 4 n-frags of 8 = 32 cols per warp

    extern __shared__ char smraw[];
    char* sp = (char*)((((uintptr_t)smraw) + 1023) & ~(uintptr_t)1023);
    const uint32_t sb = smem_u32(sp);
    const uint32_t sbA = sb + OFF_A;

    const int tid = threadIdx.x;
    const int wid = tid >> 5;
    const int l   = tid & 31;
    const int warp_m = wid & 3;      // 4-way over rows (32 each)
    const int warp_n = wid >> 2;     // 4-way over cols (32 each)

    {
        const uint4* s = (const uint4*)img;
        uint4* d = (uint4*)sp;
        for (int i = tid; i < BB / 16; i += 512) d[i] = s[i];
    }

    const uint32_t xorm = (uint32_t)(l & 7) << 4;
    const uint32_t aRow = warp_m * 32 + (l & 15);
    const uint32_t aK16 = (uint32_t)(l >> 4);
    const uint32_t bN   = warp_n * 32 + (l & 7);
    const uint32_t bK16 = (uint32_t)((l >> 3) & 1);
    const int g  = l >> 2;
    const int t2 = (l & 3) * 2;

    for (int tile = blockIdx.x; tile < ntiles; tile += gridDim.x) {
        const int blockRow = tile * 128;

        float acc[2][NF][4];
        #pragma unroll
        for (int i = 0; i < 2; i++)
            #pragma unroll
            for (int j = 0; j < NF; j++)
                #pragma unroll
                for (int q = 0; q < 4; q++) acc[i][j][q] = 0.f;

        #pragma unroll
        for (int v = 0; v < 4; v++) {
            int vid = tid + v * 512;
            int row = vid >> 4;
            int u   = vid & 15;
            int grow = blockRow + row;
            bool valid = grow < M;
            const float* src = A + (size_t)(valid ? grow : 0) * lda + u * 4;
            uint32_t dst = sbA + row * 256 + (((uint32_t)u * 16) ^ (((uint32_t)row & 7) << 4));
            cp16(dst, src, valid);
        }
        CP_COMMIT();

        for (int c = 0; c < KCH; c++) {
            const int buf = c & 1;
            if (c + 1 < KCH) {
                const int nb = (c + 1) & 1;
                #pragma unroll
                for (int v = 0; v < 4; v++) {
                    int vid = tid + v * 512;
                    int row = vid >> 4;
                    int u   = vid & 15;
                    int grow = blockRow + row;
                    bool valid = grow < M;
                    const float* src = A + (size_t)(valid ? grow : 0) * lda + (c + 1) * 64 + u * 4;
                    uint32_t dst = sbA + nb * ASTG + row * 256
                                 + (((uint32_t)u * 16) ^ (((uint32_t)row & 7) << 4));
                    cp16(dst, src, valid);
                }
                CP_COMMIT();
                CP_WAIT(1);
            } else {
                CP_WAIT(0);
            }
            __syncthreads();

            const uint32_t aB = sbA + buf * ASTG;
            const uint32_t bB = sb + c * BCH;
            #pragma unroll
            for (int s = 0; s < 8; s++) {
                const uint32_t koff = (uint32_t)s * 32;
                uint32_t bf[NF][2];
                #pragma unroll
                for (int j = 0; j < NF; j++)
                    ldsm_x2(bf[j], bB + (bN + j * 8) * 256 + ((koff + bK16 * 16) ^ xorm));
                #pragma unroll
                for (int i = 0; i < 2; i++) {
                    uint32_t af[4];
                    ldsm_x4(af, aB + (aRow + i * 16) * 256 + ((koff + aK16 * 16) ^ xorm));
                    #pragma unroll
                    for (int j = 0; j < NF; j++)
                        mma_tf32(acc[i][j], af, bf[j]);
                }
            }
            __syncthreads();
        }

        #pragma unroll
        for (int i = 0; i < 2; i++) {
            int row0 = blockRow + warp_m * 32 + i * 16 + g;
            #pragma unroll
            for (int j = 0; j < NF; j++) {
                int col = warp_n * 32 + j * 8 + t2;
                if (row0 < M) {
                    __nv_bfloat162 v = __floats2bfloat162_rn(acc[i][j][0], acc[i][j][1]);
                    *(__nv_bfloat162*)(C + (size_t)row0 * NT + col) = v;
                }
                if (row0 + 8 < M) {
                    __nv_bfloat162 v = __floats2bfloat162_rn(acc[i][j][2], acc[i][j][3]);
                    *(__nv_bfloat162*)(C + (size_t)(row0 + 8) * NT + col) = v;
                }
            }
        }
    }
}

// ================= GEMM2: persistent bf16 2-term, cp.async, 2 CTA/SM ===========
__global__ __launch_bounds__(256, 2)
void bf16_gemm(const __nv_bfloat16* __restrict__ A, int lda,
               const __nv_bfloat16* __restrict__ imgHi, const __nv_bfloat16* __restrict__ imgLo,
               __nv_bfloat16* __restrict__ C, int M, int ntiles)
{
    constexpr int NT  = OUTF;
    constexpr int KCH = 2;
    constexpr int BCH = NT * 128;
    constexpr int BB  = KCH * BCH;
    constexpr int OFF_BLO = BB;
    constexpr int OFF_A   = 2 * BB;
    constexpr int ASTG = 16384;
    constexpr int NTW = NT / 4;
    constexpr int NF  = NTW / 8;

    extern __shared__ char smraw[];
    char* sp = (char*)((((uintptr_t)smraw) + 1023) & ~(uintptr_t)1023);
    const uint32_t sb = smem_u32(sp);
    const uint32_t sbA = sb + OFF_A;

    const int tid = threadIdx.x;
    const int wid = tid >> 5;
    const int l   = tid & 31;
    const int warp_m = wid & 1;
    const int warp_n = wid >> 1;

    {
        const uint4* shi = (const uint4*)imgHi;
        const uint4* slo = (const uint4*)imgLo;
        uint4* dhi = (uint4*)sp;
        uint4* dlo = (uint4*)(sp + OFF_BLO);
        for (int i = tid; i < BB / 16; i += 256) { dhi[i] = shi[i]; dlo[i] = slo[i]; }
    }

    const uint32_t xorm = (uint32_t)(l & 7) << 4;
    const uint32_t aRow = warp_m * 64 + (l & 15);
    const uint32_t aK8  = (uint32_t)(l >> 4) * 8;
    const uint32_t bN   = warp_n * NTW + (l & 7);
    const uint32_t bK8  = (uint32_t)((l >> 3) & 1) * 8;
    const int g  = l >> 2;
    const int t2 = (l & 3) * 2;

    for (int tile = blockIdx.x; tile < ntiles; tile += gridDim.x) {
        const int blockRow = tile * 128;

        float acc[4][NF][4];
        #pragma unroll
        for (int i = 0; i < 4; i++)
            #pragma unroll
            for (int j = 0; j < NF; j++)
                #pragma unroll
                for (int q = 0; q < 4; q++) acc[i][j][q] = 0.f;

        #pragma unroll
        for (int v = 0; v < 4; v++) {
            int vid = tid + v * 256;
            int row = vid >> 3;
            int u   = vid & 7;
            int grow = blockRow + row;
            bool valid = grow < M;
            const __nv_bfloat16* src = A + (size_t)(valid ? grow : 0) * lda + u * 8;
            uint32_t dst = sbA + row * 128 + (((uint32_t)u * 16) ^ (((uint32_t)row & 7) << 4));
            cp16(dst, src, valid);
        }
        CP_COMMIT();

        for (int c = 0; c < KCH; c++) {
            const int buf = c & 1;
            if (c + 1 < KCH) {
                const int nb = (c + 1) & 1;
                #pragma unroll
                for (int v = 0; v < 4; v++) {
                    int vid = tid + v * 256;
                    int row = vid >> 3;
                    int u   = vid & 7;
                    int grow = blockRow + row;
                    bool valid = grow < M;
                    const __nv_bfloat16* src = A + (size_t)(valid ? grow : 0) * lda + (c + 1) * 64 + u * 8;
                    uint32_t dst = sbA + nb * ASTG + row * 128
                                 + (((uint32_t)u * 16) ^ (((uint32_t)row & 7) << 4));
                    cp16(dst, src, valid);
                }
                CP_COMMIT();
                CP_WAIT(1);
            } else {
                CP_WAIT(0);
            }
            __syncthreads();

            const uint32_t aB = sbA + buf * ASTG + aRow * 128;
            const uint32_t bHiBase = sb + c * BCH + bN * 128;
            const uint32_t bLoBase = bHiBase + OFF_BLO;
            #pragma unroll
            for (int s = 0; s < 4; s++) {
                const uint32_t akOff = ((uint32_t)(s * 16 + aK8) * 2) ^ xorm;
                const uint32_t bkOff = ((uint32_t)(s * 16 + bK8) * 2) ^ xorm;
                uint32_t bh[NF][2], bl[NF][2];
                #pragma unroll
                for (int j = 0; j < NF; j++) {
                    ldsm_x2(bh[j], bHiBase + j * 1024 + bkOff);
                    ldsm_x2(bl[j], bLoBase + j * 1024 + bkOff);
                }
                #pragma unroll
                for (int i = 0; i < 4; i++) {
                    uint32_t ah[4];
                    ldsm_x4(ah, aB + i * 2048 + akOff);
                    #pragma unroll
                    for (int j = 0; j < NF; j++) {
                        mma_bf16(acc[i][j], ah, bh[j]);
                        mma_bf16(acc[i][j], ah, bl[j]);
                    }
                }
            }
            __syncthreads();
        }

        #pragma unroll
        for (int i = 0; i < 4; i++) {
            int row0 = blockRow + warp_m * 64 + i * 16 + g;
            #pragma unroll
            for (int j = 0; j < NF; j++) {
                int col = warp_n * NTW + j * 8 + t2;
                if (row0 < M) {
                    __nv_bfloat162 v = __floats2bfloat162_rn(acc[i][j][0], acc[i][j][1]);
                    *(__nv_bfloat162*)(C + (size_t)row0 * NT + col) = v;
                }
                if (row0 + 8 < M) {
                    __nv_bfloat162 v = __floats2bfloat162_rn(acc[i][j][2], acc[i][j][3]);
                    *(__nv_bfloat162*)(C + (size_t)(row0 + 8) * NT + col) = v;
                }
            }
        }
    }
}

// ================= agg1: bf16 in, bf16 out =====================================
__global__ void agg1_kernel(const __nv_bfloat16* __restrict__ h, const int* __restrict__ rowptr,
                            const int* __restrict__ adj, const float* __restrict__ dinv,
                            const float* __restrict__ b1, __nv_bfloat16* __restrict__ h2, int n)
{
    int node = (blockIdx.x * blockDim.x + threadIdx.x) >> 5;
    int lane = threadIdx.x & 31;
    if (node >= n) return;
    int beg = rowptr[node], end = rowptr[node + 1];
    float dd = dinv[node];
    size_t l4 = (size_t)lane * 4;
    float ax = 0.f, ay = 0.f, az = 0.f, aw = 0.f;
    int e = beg;
    for (; e + 1 < end; e += 2) {
        int s0 = __ldg(adj + e), s1 = __ldg(adj + e + 1);
        float n0 = __ldg(dinv + s0) * dd, n1 = __ldg(dinv + s1) * dd;
        uint2 p0 = *(const uint2*)(h + (size_t)s0 * HIDF + l4);
        uint2 p1 = *(const uint2*)(h + (size_t)s1 * HIDF + l4);
        float2 a0 = bf2f(p0.x), b0 = bf2f(p0.y);
        float2 a1 = bf2f(p1.x), b1v = bf2f(p1.y);
        ax = fmaf(n0, a0.x, ax); ay = fmaf(n0, a0.y, ay);
        az = fmaf(n0, b0.x, az); aw = fmaf(n0, b0.y, aw);
        ax = fmaf(n1, a1.x, ax); ay = fmaf(n1, a1.y, ay);
        az = fmaf(n1, b1v.x, az); aw = fmaf(n1, b1v.y, aw);
    }
    if (e < end) {
        int s0 = __ldg(adj + e);
        float n0 = __ldg(dinv + s0) * dd;
        uint2 p0 = *(const uint2*)(h + (size_t)s0 * HIDF + l4);
        float2 a0 = bf2f(p0.x), b0 = bf2f(p0.y);
        ax = fmaf(n0, a0.x, ax); ay = fmaf(n0, a0.y, ay);
        az = fmaf(n0, b0.x, az); aw = fmaf(n0, b0.y, aw);
    }
    float d2 = dd * dd;
    uint2 ps = *(const uint2*)(h + (size_t)node * HIDF + l4);
    float2 s01 = bf2f(ps.x), s23 = bf2f(ps.y);
    float4 bv = *(const float4*)(b1 + l4);
    float tx_ = fmaf(d2, s01.x, ax) + bv.x;
    float ty_ = fmaf(d2, s01.y, ay) + bv.y;
    float tz_ = fmaf(d2, s23.x, az) + bv.z;
    float tw_ = fmaf(d2, s23.y, aw) + bv.w;
    float ox = 0.9f * fmaxf(tx_, 0.f) + 0.1f;
    float oy = 0.9f * fmaxf(ty_, 0.f) + 0.1f;
    float oz = 0.9f * fmaxf(tz_, 0.f) + 0.1f;
    float ow = 0.9f * fmaxf(tw_, 0.f) + 0.1f;
    __nv_bfloat162 o01 = __floats2bfloat162_rn(ox, oy);
    __nv_bfloat162 o23 = __floats2bfloat162_rn(oz, ow);
    uint2 st;
    st.x = *reinterpret_cast<uint32_t*>(&o01);
    st.y = *reinterpret_cast<uint32_t*>(&o23);
    *(uint2*)(h2 + (size_t)node * HIDF + l4) = st;
}

// ================= agg2: bf16 in, fp32 log-softmax out =========================
__global__ void agg2_kernel(const __nv_bfloat16* __restrict__ g, const int* __restrict__ rowptr,
                            const int* __restrict__ adj, const float* __restrict__ dinv,
                            const float* __restrict__ b2, float* __restrict__ out, int n)
{
    int node = (blockIdx.x * blockDim.x + threadIdx.x) >> 4;
    int sub  = threadIdx.x & 15;
    if (node >= n) return;
    int beg = rowptr[node], end = rowptr[node + 1];
    float dd = dinv[node];
    size_t l4 = (size_t)sub * 4;
    float ax = 0.f, ay = 0.f, az = 0.f, aw = 0.f;
    int e = beg;
    for (; e + 1 < end; e += 2) {
        int s0 = __ldg(adj + e), s1 = __ldg(adj + e + 1);
        float n0 = __ldg(dinv + s0) * dd, n1 = __ldg(dinv + s1) * dd;
        uint2 p0 = *(const uint2*)(g + (size_t)s0 * OUTF + l4);
        uint2 p1 = *(const uint2*)(g + (size_t)s1 * OUTF + l4);
        float2 a0 = bf2f(p0.x), b0 = bf2f(p0.y);
        float2 a1 = bf2f(p1.x), b1v = bf2f(p1.y);
        ax = fmaf(n0, a0.x, ax); ay = fmaf(n0, a0.y, ay);
        az = fmaf(n0, b0.x, az); aw = fmaf(n0, b0.y, aw);
        ax = fmaf(n1, a1.x, ax); ay = fmaf(n1, a1.y, ay);
        az = fmaf(n1, b1v.x, az); aw = fmaf(n1, b1v.y, aw);
    }
    if (e < end) {
        int s0 = __ldg(adj + e);
        float n0 = __ldg(dinv + s0) * dd;
        uint2 p0 = *(const uint2*)(g + (size_t)s0 * OUTF + l4);
        float2 a0 = bf2f(p0.x), b0 = bf2f(p0.y);
        ax = fmaf(n0, a0.x, ax); ay = fmaf(n0, a0.y, ay);
        az = fmaf(n0, b0.x, az); aw = fmaf(n0, b0.y, aw);
    }
    float d2 = dd * dd;
    uint2 ps = *(const uint2*)(g + (size_t)node * OUTF + l4);
    float2 s01 = bf2f(ps.x), s23 = bf2f(ps.y);
    float4 bv = *(const float4*)(b2 + l4);
    float v0 = fmaf(d2, s01.x, ax) + bv.x;
    float v1 = fmaf(d2, s01.y, ay) + bv.y;
    float v2 = fmaf(d2, s23.x, az) + bv.z;
    float v3 = fmaf(d2, s23.y, aw) + bv.w;
    float m = fmaxf(fmaxf(v0, v1), fmaxf(v2, v3));
    #pragma unroll
    for (int o = 8; o > 0; o >>= 1) m = fmaxf(m, __shfl_xor_sync(~0u, m, o, 16));
    float s = expf(v0 - m) + expf(v1 - m) + expf(v2 - m) + expf(v3 - m);
    #pragma unroll
    for (int o = 8; o > 0; o >>= 1) s += __shfl_xor_sync(~0u, s, o, 16);
    float ls = m + logf(s);
    float4 r = make_float4(v0 - ls, v1 - ls, v2 - ls, v3 - ls);
    *(float4*)(out + (size_t)node * OUTF + l4) = r;
}

// ================= launch =======================================================
extern "C" void kernel_launch(void* const* d_in, const int* in_sizes, int n_in,
                              void* d_out, int out_size)
{
    const float* x  = (const float*)d_in[0];
    const int*   ei = (const int*)  d_in[1];
    // d_in[2] edge_weight: unused (CRF softmax over singleton groups == 1.0)
    const float* W1 = (const float*)d_in[3];
    const float* b1 = (const float*)d_in[4];
    const float* W2 = (const float*)d_in[5];
    const float* b2 = (const float*)d_in[6];
    float* out = (float*)d_out;

    const int n = in_sizes[0] / INF;
    const int E = in_sizes[2];
    const int* src = ei;
    const int* dst = ei + E;

    __nv_bfloat16 *h, *h2, *g, *w2hi, *w2lo;
    float *dinv, *w1t;
    int *cnt, *rowptr, *cursor, *adj, *bsum, *boff;
    cudaGetSymbolAddress((void**)&h,     g_h);
    cudaGetSymbolAddress((void**)&h2,    g_h2);
    cudaGetSymbolAddress((void**)&g,     g_g);
    cudaGetSymbolAddress((void**)&dinv,  g_dinv);
    cudaGetSymbolAddress((void**)&cnt,   g_cnt);
    cudaGetSymbolAddress((void**)&rowptr,g_rowptr);
    cudaGetSymbolAddress((void**)&cursor,g_cursor);
    cudaGetSymbolAddress((void**)&adj,   g_adj);
    cudaGetSymbolAddress((void**)&bsum,  g_bsum);
    cudaGetSymbolAddress((void**)&boff,  g_boff);
    cudaGetSymbolAddress((void**)&w1t,   g_w1t);
    cudaGetSymbolAddress((void**)&w2hi,  g_w2hi);
    cudaGetSymbolAddress((void**)&w2lo,  g_w2lo);

    const int nb = (n + SCAN_BS - 1) / SCAN_BS;
    const int mtiles = (n + 127) / 128;

    constexpr int SMEM1 = INF * HIDF * 4 + 2 * 32768 + 1024;
    constexpr int SMEM2 = 2 * (HIDF * OUTF * 2) + 2 * 16384 + 1024;
    cudaFuncSetAttribute(tf32_gemm, cudaFuncAttributeMaxDynamicSharedMemorySize, SMEM1);
    cudaFuncSetAttribute(bf16_gemm, cudaFuncAttributeMaxDynamicSharedMemorySize, SMEM2);

    // side stream + events: created once on the (uncaptured) correctness call,
    // reused during graph capture via standard capture-fork event edges.
    static cudaStream_t sCsr = nullptr;
    static cudaEvent_t evFork = nullptr, evJoin = nullptr;
    if (!sCsr) {
        cudaStreamCreateWithFlags(&sCsr, cudaStreamNonBlocking);
        cudaEventCreateWithFlags(&evFork, cudaEventDisableTiming);
        cudaEventCreateWithFlags(&evJoin, cudaEventDisableTiming);
    }

    // fork: CSR build + W2 prep on side stream, GEMM1 path on main stream
    cudaEventRecord(evFork, 0);
    cudaStreamWaitEvent(sCsr, evFork, 0);

    cudaMemsetAsync(cnt, 0, (size_t)n * sizeof(int), sCsr);
    count_kernel<<<(E + 255)/256, 256, 0, sCsr>>>(dst, E, cnt);
    scanA_kernel<<<nb, SCAN_BS, 0, sCsr>>>(cnt, n, bsum);
    scanB_kernel<<<1, 128, 0, sCsr>>>(bsum, nb, boff, rowptr, n, E);
    scanC_kernel<<<nb, SCAN_BS, 0, sCsr>>>(cnt, boff, n, rowptr, cursor, dinv);
    fill_kernel <<<(E + 255)/256, 256, 0, sCsr>>>(src, dst, E, cursor, adj);
    wsplit_kernel<<<(HIDF*OUTF + 255)/256, 256, 0, sCsr>>>(W2, HIDF, OUTF, w2hi, w2lo);
    cudaEventRecord(evJoin, sCsr);

    // main stream: GEMM1 (runs concurrently with CSR build)
    wtf32_kernel<<<(INF*HIDF + 255)/256, 256>>>(W1, INF, HIDF, w1t);
    tf32_gemm<<<148, 512, SMEM1>>>(x, INF, w1t, h, n, mtiles);

    // join
    cudaStreamWaitEvent(0, evJoin, 0);

    agg1_kernel<<<((long long)n*32 + 255)/256, 256>>>(h, rowptr, adj, dinv, b1, h2, n);
    bf16_gemm<<<296, 256, SMEM2>>>(h2, HIDF, w2hi, w2lo, g, n, mtiles);
    agg2_kernel<<<((long long)n*16 + 255)/256, 256>>>(g, rowptr, adj, dinv, b2, out, n);
}

// round 9
// speedup vs baseline: 3.3866x; 1.0849x over previous
#include <cuda_runtime.h>
#include <cuda_bf16.h>
#include <cstdint>

#define MAX_NODES 100000
#define MAX_EDGES 1600000
#define INF  256
#define HIDF 128
#define OUTF 64
#define SCAN_BS 1024

// ---------------- device scratch ----------------------------------------------
__device__ __align__(128) __nv_bfloat16 g_h  [(size_t)MAX_NODES * HIDF];
__device__ __align__(128) __nv_bfloat16 g_h2 [(size_t)MAX_NODES * HIDF];
__device__ __align__(128) __nv_bfloat16 g_g  [(size_t)MAX_NODES * OUTF];
__device__ __align__(128) float g_dinv[MAX_NODES];
__device__ __align__(128) int   g_cnt   [MAX_NODES];
__device__ __align__(128) int   g_rowptr[MAX_NODES + 1];
__device__ __align__(128) int   g_cursor[MAX_NODES];
__device__ __align__(128) int   g_adj   [MAX_EDGES];
__device__ __align__(128) int   g_bsum  [256];
__device__ __align__(128) int   g_boff  [256];
__device__ __align__(128) float g_w1t [INF * HIDF];
__device__ __align__(128) __nv_bfloat16 g_w2hi[HIDF * OUTF];
__device__ __align__(128) __nv_bfloat16 g_w2lo[HIDF * OUTF];

// ================= helpers ======================================================
__device__ __forceinline__ uint32_t smem_u32(const void* p) {
    uint32_t a;
    asm("{ .reg .u64 t; cvta.to.shared.u64 t, %1; cvt.u32.u64 %0, t; }" : "=r"(a) : "l"(p));
    return a;
}
__device__ __forceinline__ void ldsm_x4(uint32_t* r, uint32_t addr) {
    asm volatile("ldmatrix.sync.aligned.m8n8.x4.shared.b16 {%0,%1,%2,%3}, [%4];"
                 : "=r"(r[0]), "=r"(r[1]), "=r"(r[2]), "=r"(r[3]) : "r"(addr));
}
__device__ __forceinline__ void ldsm_x2(uint32_t* r, uint32_t addr) {
    asm volatile("ldmatrix.sync.aligned.m8n8.x2.shared.b16 {%0,%1}, [%2];"
                 : "=r"(r[0]), "=r"(r[1]) : "r"(addr));
}
__device__ __forceinline__ void mma_bf16(float* d, const uint32_t* a, const uint32_t* b) {
    asm volatile(
        "mma.sync.aligned.m16n8k16.row.col.f32.bf16.bf16.f32 "
        "{%0,%1,%2,%3}, {%4,%5,%6,%7}, {%8,%9}, {%0,%1,%2,%3};"
        : "+f"(d[0]), "+f"(d[1]), "+f"(d[2]), "+f"(d[3])
        : "r"(a[0]), "r"(a[1]), "r"(a[2]), "r"(a[3]), "r"(b[0]), "r"(b[1]));
}
__device__ __forceinline__ void mma_tf32(float* d, const uint32_t* a, const uint32_t* b) {
    asm volatile(
        "mma.sync.aligned.m16n8k8.row.col.f32.tf32.tf32.f32 "
        "{%0,%1,%2,%3}, {%4,%5,%6,%7}, {%8,%9}, {%0,%1,%2,%3};"
        : "+f"(d[0]), "+f"(d[1]), "+f"(d[2]), "+f"(d[3])
        : "r"(a[0]), "r"(a[1]), "r"(a[2]), "r"(a[3]), "r"(b[0]), "r"(b[1]));
}
__device__ __forceinline__ void cp16(uint32_t dst, const void* src, bool valid) {
    int sz = valid ? 16 : 0;
    asm volatile("cp.async.cg.shared.global [%0], [%1], 16, %2;"
                 :: "r"(dst), "l"(src), "r"(sz) : "memory");
}
#define CP_COMMIT() asm volatile("cp.async.commit_group;" ::: "memory")
#define CP_WAIT(n)  asm volatile("cp.async.wait_group %0;" :: "n"(n) : "memory")

// exact bf16x2 -> 2x f32 via bit ops (ALU pipe, no CVT)
__device__ __forceinline__ void bq8(const uint4& q, float* f) {
    f[0] = __uint_as_float(q.x << 16); f[1] = __uint_as_float(q.x & 0xffff0000u);
    f[2] = __uint_as_float(q.y << 16); f[3] = __uint_as_float(q.y & 0xffff0000u);
    f[4] = __uint_as_float(q.z << 16); f[5] = __uint_as_float(q.z & 0xffff0000u);
    f[6] = __uint_as_float(q.w << 16); f[7] = __uint_as_float(q.w & 0xffff0000u);
}
__device__ __forceinline__ void acc8(float* acc, const uint4& q, float nrm) {
    float f[8]; bq8(q, f);
    #pragma unroll
    for (int i = 0; i < 8; i++) acc[i] = fmaf(nrm, f[i], acc[i]);
}

// ================= CSR build ====================================================
__global__ void count_kernel(const int* __restrict__ dst, int E, int* __restrict__ cnt) {
    int i = blockIdx.x * blockDim.x + threadIdx.x;
    if (i < E) atomicAdd(&cnt[dst[i]], 1);
}
__global__ void scanA_kernel(const int* __restrict__ cnt, int n, int* __restrict__ bsum) {
    int i = blockIdx.x * SCAN_BS + threadIdx.x;
    int c = (i < n) ? cnt[i] : 0;
    int lane = threadIdx.x & 31, wid = threadIdx.x >> 5;
    #pragma unroll
    for (int o = 16; o > 0; o >>= 1) c += __shfl_xor_sync(~0u, c, o);
    __shared__ int ws[32];
    if (lane == 0) ws[wid] = c;
    __syncthreads();
    if (threadIdx.x < 32) {
        int v = ws[threadIdx.x];
        #pragma unroll
        for (int o = 16; o > 0; o >>= 1) v += __shfl_xor_sync(~0u, v, o);
        if (threadIdx.x == 0) bsum[blockIdx.x] = v;
    }
}
__global__ void scanB_kernel(const int* __restrict__ bsum, int nb,
                             int* __restrict__ boff, int* __restrict__ rowptr,
                             int n, int E) {
    int t = threadIdx.x;
    int v = (t < nb) ? bsum[t] : 0;
    int lane = t & 31, w = t >> 5;
    int incl = v;
    #pragma unroll
    for (int o = 1; o < 32; o <<= 1) {
        int u = __shfl_up_sync(~0u, incl, o);
        if (lane >= o) incl += u;
    }
    __shared__ int ws[4];
    if (lane == 31) ws[w] = incl;
    __syncthreads();
    int add = 0;
    #pragma unroll
    for (int k = 0; k < 4; k++) if (k < w) add += ws[k];
    if (t < nb) boff[t] = incl - v + add;
    if (t == 0) rowptr[n] = E;
}
__global__ void scanC_kernel(const int* __restrict__ cnt, const int* __restrict__ boff,
                             int n, int* __restrict__ rowptr, int* __restrict__ cursor,
                             float* __restrict__ dinv) {
    int i = blockIdx.x * SCAN_BS + threadIdx.x;
    int c = (i < n) ? cnt[i] : 0;
    int lane = threadIdx.x & 31, wid = threadIdx.x >> 5;
    int v = c;
    #pragma unroll
    for (int o = 1; o < 32; o <<= 1) {
        int t = __shfl_up_sync(~0u, v, o);
        if (lane >= o) v += t;
    }
    __shared__ int ws[32];
    if (lane == 31) ws[wid] = v;
    __syncthreads();
    if (threadIdx.x < 32) {
        int w = ws[threadIdx.x];
        #pragma unroll
        for (int o = 1; o < 32; o <<= 1) {
            int t = __shfl_up_sync(~0u, w, o);
            if ((int)threadIdx.x >= o) w += t;
        }
        ws[threadIdx.x] = w;
    }
    __syncthreads();
    int excl = v - c + (wid > 0 ? ws[wid - 1] : 0) + boff[blockIdx.x];
    if (i < n) {
        rowptr[i] = excl;
        cursor[i] = excl;
        dinv[i] = rsqrtf((float)c + 1.0f);
    }
}
__global__ void fill_kernel(const int* __restrict__ src, const int* __restrict__ dst,
                            int E, int* __restrict__ cursor, int* __restrict__ adj) {
    int i = blockIdx.x * blockDim.x + threadIdx.x;
    if (i < E) {
        int pos = atomicAdd(&cursor[dst[i]], 1);
        adj[pos] = src[i];
    }
}

// ================= weight prep ==================================================
__global__ void wtf32_kernel(const float* __restrict__ W, int K, int N,
                             float* __restrict__ img) {
    int idx = blockIdx.x * blockDim.x + threadIdx.x;
    if (idx >= K * N) return;
    int k = idx / N, n = idx % N;
    int c = k >> 6, kk = k & 63;
    uint32_t off = (uint32_t)(n * 256 + kk * 4);
    uint32_t sw = off ^ (((off >> 8) & 7) << 4);
    img[((size_t)c * N * 256 + sw) / 4] = W[(size_t)k * N + n];
}
__global__ void wsplit_kernel(const float* __restrict__ W, int K, int N,
                              __nv_bfloat16* __restrict__ hi, __nv_bfloat16* __restrict__ lo) {
    int idx = blockIdx.x * blockDim.x + threadIdx.x;
    if (idx >= K * N) return;
    int k = idx / N, n = idx % N;
    float w = W[(size_t)k * N + n];
    __nv_bfloat16 h = __float2bfloat16(w);
    __nv_bfloat16 l = __float2bfloat16(w - __bfloat162float(h));
    int c = k >> 6, kk = k & 63;
    uint32_t off = (uint32_t)(n * 128 + kk * 2);
    uint32_t sw = off ^ ((off >> 3) & 0x70);
    size_t pos = ((size_t)c * N * 128 + sw) / 2;
    hi[pos] = h;
    lo[pos] = l;
}

// ================= GEMM1: persistent tf32, 512 threads, cp.async ==============
__global__ __launch_bounds__(512, 1)
void tf32_gemm(const float* __restrict__ A, int lda, const float* __restrict__ img,
               __nv_bfloat16* __restrict__ C, int M, int ntiles)
{
    constexpr int NT  = HIDF;
    constexpr int KCH = 4;
    constexpr int BCH = NT * 256;
    constexpr int BB  = KCH * BCH;
    constexpr int OFF_A = BB;
    constexpr int ASTG = 32768;
    constexpr int NF  = 4;

    extern __shared__ char smraw[];
    char* sp = (char*)((((uintptr_t)smraw) + 1023) & ~(uintptr_t)1023);
    const uint32_t sb = smem_u32(sp);
    const uint32_t sbA = sb + OFF_A;

    const int tid = threadIdx.x;
    const int wid = tid >> 5;
    const int l   = tid & 31;
    const int warp_m = wid & 3;
    const int warp_n = wid >> 2;

    {
        const uint4* s = (const uint4*)img;
        uint4* d = (uint4*)sp;
        for (int i = tid; i < BB / 16; i += 512) d[i] = s[i];
    }

    const uint32_t xorm = (uint32_t)(l & 7) << 4;
    const uint32_t aRow = warp_m * 32 + (l & 15);
    const uint32_t aK16 = (uint32_t)(l >> 4);
    const uint32_t bN   = warp_n * 32 + (l & 7);
    const uint32_t bK16 = (uint32_t)((l >> 3) & 1);
    const int g  = l >> 2;
    const int t2 = (l & 3) * 2;

    for (int tile = blockIdx.x; tile < ntiles; tile += gridDim.x) {
        const int blockRow = tile * 128;

        float acc[2][NF][4];
        #pragma unroll
        for (int i = 0; i < 2; i++)
            #pragma unroll
            for (int j = 0; j < NF; j++)
                #pragma unroll
                for (int q = 0; q < 4; q++) acc[i][j][q] = 0.f;

        #pragma unroll
        for (int v = 0; v < 4; v++) {
            int vid = tid + v * 512;
            int row = vid >> 4;
            int u   = vid & 15;
            int grow = blockRow + row;
            bool valid = grow < M;
            const float* src = A + (size_t)(valid ? grow : 0) * lda + u * 4;
            uint32_t dst = sbA + row * 256 + (((uint32_t)u * 16) ^ (((uint32_t)row & 7) << 4));
            cp16(dst, src, valid);
        }
        CP_COMMIT();

        for (int c = 0; c < KCH; c++) {
            const int buf = c & 1;
            if (c + 1 < KCH) {
                const int nb = (c + 1) & 1;
                #pragma unroll
                for (int v = 0; v < 4; v++) {
                    int vid = tid + v * 512;
                    int row = vid >> 4;
                    int u   = vid & 15;
                    int grow = blockRow + row;
                    bool valid = grow < M;
                    const float* src = A + (size_t)(valid ? grow : 0) * lda + (c + 1) * 64 + u * 4;
                    uint32_t dst = sbA + nb * ASTG + row * 256
                                 + (((uint32_t)u * 16) ^ (((uint32_t)row & 7) << 4));
                    cp16(dst, src, valid);
                }
                CP_COMMIT();
                CP_WAIT(1);
            } else {
                CP_WAIT(0);
            }
            __syncthreads();

            const uint32_t aB = sbA + buf * ASTG;
            const uint32_t bB = sb + c * BCH;
            #pragma unroll
            for (int s = 0; s < 8; s++) {
                const uint32_t koff = (uint32_t)s * 32;
                uint32_t bf[NF][2];
                #pragma unroll
                for (int j = 0; j < NF; j++)
                    ldsm_x2(bf[j], bB + (bN + j * 8) * 256 + ((koff + bK16 * 16) ^ xorm));
                #pragma unroll
                for (int i = 0; i < 2; i++) {
                    uint32_t af[4];
                    ldsm_x4(af, aB + (aRow + i * 16) * 256 + ((koff + aK16 * 16) ^ xorm));
                    #pragma unroll
                    for (int j = 0; j < NF; j++)
                        mma_tf32(acc[i][j], af, bf[j]);
                }
            }
            __syncthreads();
        }

        #pragma unroll
        for (int i = 0; i < 2; i++) {
            int row0 = blockRow + warp_m * 32 + i * 16 + g;
            #pragma unroll
            for (int j = 0; j < NF; j++) {
                int col = warp_n * 32 + j * 8 + t2;
                if (row0 < M) {
                    __nv_bfloat162 v = __floats2bfloat162_rn(acc[i][j][0], acc[i][j][1]);
                    *(__nv_bfloat162*)(C + (size_t)row0 * NT + col) = v;
                }
                if (row0 + 8 < M) {
                    __nv_bfloat162 v = __floats2bfloat162_rn(acc[i][j][2], acc[i][j][3]);
                    *(__nv_bfloat162*)(C + (size_t)(row0 + 8) * NT + col) = v;
                }
            }
        }
    }
}

// ================= GEMM2: persistent bf16 2-term, cp.async, 2 CTA/SM ===========
__global__ __launch_bounds__(256, 2)
void bf16_gemm(const __nv_bfloat16* __restrict__ A, int lda,
               const __nv_bfloat16* __restrict__ imgHi, const __nv_bfloat16* __restrict__ imgLo,
               __nv_bfloat16* __restrict__ C, int M, int ntiles)
{
    constexpr int NT  = OUTF;
    constexpr int KCH = 2;
    constexpr int BCH = NT * 128;
    constexpr int BB  = KCH * BCH;
    constexpr int OFF_BLO = BB;
    constexpr int OFF_A   = 2 * BB;
    constexpr int ASTG = 16384;
    constexpr int NTW = NT / 4;
    constexpr int NF  = NTW / 8;

    extern __shared__ char smraw[];
    char* sp = (char*)((((uintptr_t)smraw) + 1023) & ~(uintptr_t)1023);
    const uint32_t sb = smem_u32(sp);
    const uint32_t sbA = sb + OFF_A;

    const int tid = threadIdx.x;
    const int wid = tid >> 5;
    const int l   = tid & 31;
    const int warp_m = wid & 1;
    const int warp_n = wid >> 1;

    {
        const uint4* shi = (const uint4*)imgHi;
        const uint4* slo = (const uint4*)imgLo;
        uint4* dhi = (uint4*)sp;
        uint4* dlo = (uint4*)(sp + OFF_BLO);
        for (int i = tid; i < BB / 16; i += 256) { dhi[i] = shi[i]; dlo[i] = slo[i]; }
    }

    const uint32_t xorm = (uint32_t)(l & 7) << 4;
    const uint32_t aRow = warp_m * 64 + (l & 15);
    const uint32_t aK8  = (uint32_t)(l >> 4) * 8;
    const uint32_t bN   = warp_n * NTW + (l & 7);
    const uint32_t bK8  = (uint32_t)((l >> 3) & 1) * 8;
    const int g  = l >> 2;
    const int t2 = (l & 3) * 2;

    for (int tile = blockIdx.x; tile < ntiles; tile += gridDim.x) {
        const int blockRow = tile * 128;

        float acc[4][NF][4];
        #pragma unroll
        for (int i = 0; i < 4; i++)
            #pragma unroll
            for (int j = 0; j < NF; j++)
                #pragma unroll
                for (int q = 0; q < 4; q++) acc[i][j][q] = 0.f;

        #pragma unroll
        for (int v = 0; v < 4; v++) {
            int vid = tid + v * 256;
            int row = vid >> 3;
            int u   = vid & 7;
            int grow = blockRow + row;
            bool valid = grow < M;
            const __nv_bfloat16* src = A + (size_t)(valid ? grow : 0) * lda + u * 8;
            uint32_t dst = sbA + row * 128 + (((uint32_t)u * 16) ^ (((uint32_t)row & 7) << 4));
            cp16(dst, src, valid);
        }
        CP_COMMIT();

        for (int c = 0; c < KCH; c++) {
            const int buf = c & 1;
            if (c + 1 < KCH) {
                const int nb = (c + 1) & 1;
                #pragma unroll
                for (int v = 0; v < 4; v++) {
                    int vid = tid + v * 256;
                    int row = vid >> 3;
                    int u   = vid & 7;
                    int grow = blockRow + row;
                    bool valid = grow < M;
                    const __nv_bfloat16* src = A + (size_t)(valid ? grow : 0) * lda + (c + 1) * 64 + u * 8;
                    uint32_t dst = sbA + nb * ASTG + row * 128
                                 + (((uint32_t)u * 16) ^ (((uint32_t)row & 7) << 4));
                    cp16(dst, src, valid);
                }
                CP_COMMIT();
                CP_WAIT(1);
            } else {
                CP_WAIT(0);
            }
            __syncthreads();

            const uint32_t aB = sbA + buf * ASTG + aRow * 128;
            const uint32_t bHiBase = sb + c * BCH + bN * 128;
            const uint32_t bLoBase = bHiBase + OFF_BLO;
            #pragma unroll
            for (int s = 0; s < 4; s++) {
                const uint32_t akOff = ((uint32_t)(s * 16 + aK8) * 2) ^ xorm;
                const uint32_t bkOff = ((uint32_t)(s * 16 + bK8) * 2) ^ xorm;
                uint32_t bh[NF][2], bl[NF][2];
                #pragma unroll
                for (int j = 0; j < NF; j++) {
                    ldsm_x2(bh[j], bHiBase + j * 1024 + bkOff);
                    ldsm_x2(bl[j], bLoBase + j * 1024 + bkOff);
                }
                #pragma unroll
                for (int i = 0; i < 4; i++) {
                    uint32_t ah[4];
                    ldsm_x4(ah, aB + i * 2048 + akOff);
                    #pragma unroll
                    for (int j = 0; j < NF; j++) {
                        mma_bf16(acc[i][j], ah, bh[j]);
                        mma_bf16(acc[i][j], ah, bl[j]);
                    }
                }
            }
            __syncthreads();
        }

        #pragma unroll
        for (int i = 0; i < 4; i++) {
            int row0 = blockRow + warp_m * 64 + i * 16 + g;
            #pragma unroll
            for (int j = 0; j < NF; j++) {
                int col = warp_n * NTW + j * 8 + t2;
                if (row0 < M) {
                    __nv_bfloat162 v = __floats2bfloat162_rn(acc[i][j][0], acc[i][j][1]);
                    *(__nv_bfloat162*)(C + (size_t)row0 * NT + col) = v;
                }
                if (row0 + 8 < M) {
                    __nv_bfloat162 v = __floats2bfloat162_rn(acc[i][j][2], acc[i][j][3]);
                    *(__nv_bfloat162*)(C + (size_t)(row0 + 8) * NT + col) = v;
                }
            }
        }
    }
}

// ================= agg1: 16 lanes/node, uint4 loads, 4-edge unroll =============
__global__ void agg1_kernel(const __nv_bfloat16* __restrict__ h, const int* __restrict__ rowptr,
                            const int* __restrict__ adj, const float* __restrict__ dinv,
                            const float* __restrict__ b1, __nv_bfloat16* __restrict__ h2, int n)
{
    int node = (blockIdx.x * blockDim.x + threadIdx.x) >> 4;
    int sub  = threadIdx.x & 15;
    if (node >= n) return;
    int beg = rowptr[node], end = rowptr[node + 1];
    float dd = dinv[node];
    const size_t fo = (size_t)sub * 8;

    float acc[8];
    #pragma unroll
    for (int i = 0; i < 8; i++) acc[i] = 0.f;

    int e = beg;
    for (; e + 4 <= end; e += 4) {
        int s0 = __ldg(adj + e),     s1 = __ldg(adj + e + 1);
        int s2 = __ldg(adj + e + 2), s3 = __ldg(adj + e + 3);
        float n0 = __ldg(dinv + s0) * dd, n1 = __ldg(dinv + s1) * dd;
        float n2 = __ldg(dinv + s2) * dd, n3 = __ldg(dinv + s3) * dd;
        uint4 q0 = *(const uint4*)(h + (size_t)s0 * HIDF + fo);
        uint4 q1 = *(const uint4*)(h + (size_t)s1 * HIDF + fo);
        uint4 q2 = *(const uint4*)(h + (size_t)s2 * HIDF + fo);
        uint4 q3 = *(const uint4*)(h + (size_t)s3 * HIDF + fo);
        acc8(acc, q0, n0); acc8(acc, q1, n1); acc8(acc, q2, n2); acc8(acc, q3, n3);
    }
    for (; e < end; e++) {
        int s0 = __ldg(adj + e);
        float n0 = __ldg(dinv + s0) * dd;
        uint4 q0 = *(const uint4*)(h + (size_t)s0 * HIDF + fo);
        acc8(acc, q0, n0);
    }

    float d2 = dd * dd;
    uint4 qs = *(const uint4*)(h + (size_t)node * HIDF + fo);
    float sf[8]; bq8(qs, sf);
    float4 bv0 = *(const float4*)(b1 + fo);
    float4 bv1 = *(const float4*)(b1 + fo + 4);
    float bb[8] = {bv0.x, bv0.y, bv0.z, bv0.w, bv1.x, bv1.y, bv1.z, bv1.w};
    uint32_t o[4];
    #pragma unroll
    for (int i = 0; i < 4; i++) {
        float t0 = fmaf(d2, sf[2*i],   acc[2*i])   + bb[2*i];
        float t1 = fmaf(d2, sf[2*i+1], acc[2*i+1]) + bb[2*i+1];
        float r0 = 0.9f * fmaxf(t0, 0.f) + 0.1f;
        float r1 = 0.9f * fmaxf(t1, 0.f) + 0.1f;
        __nv_bfloat162 p = __floats2bfloat162_rn(r0, r1);
        o[i] = *reinterpret_cast<uint32_t*>(&p);
    }
    *(uint4*)(h2 + (size_t)node * HIDF + fo) = make_uint4(o[0], o[1], o[2], o[3]);
}

// ================= agg2: 8 lanes/node, uint4 loads, 4-edge unroll ==============
__global__ void agg2_kernel(const __nv_bfloat16* __restrict__ g, const int* __restrict__ rowptr,
                            const int* __restrict__ adj, const float* __restrict__ dinv,
                            const float* __restrict__ b2, float* __restrict__ out, int n)
{
    int node = (blockIdx.x * blockDim.x + threadIdx.x) >> 3;
    int sub  = threadIdx.x & 7;
    if (node >= n) return;
    int beg = rowptr[node], end = rowptr[node + 1];
    float dd = dinv[node];
    const size_t fo = (size_t)sub * 8;

    float acc[8];
    #pragma unroll
    for (int i = 0; i < 8; i++) acc[i] = 0.f;

    int e = beg;
    for (; e + 4 <= end; e += 4) {
        int s0 = __ldg(adj + e),     s1 = __ldg(adj + e + 1);
        int s2 = __ldg(adj + e + 2), s3 = __ldg(adj + e + 3);
        float n0 = __ldg(dinv + s0) * dd, n1 = __ldg(dinv + s1) * dd;
        float n2 = __ldg(dinv + s2) * dd, n3 = __ldg(dinv + s3) * dd;
        uint4 q0 = *(const uint4*)(g + (size_t)s0 * OUTF + fo);
        uint4 q1 = *(const uint4*)(g + (size_t)s1 * OUTF + fo);
        uint4 q2 = *(const uint4*)(g + (size_t)s2 * OUTF + fo);
        uint4 q3 = *(const uint4*)(g + (size_t)s3 * OUTF + fo);
        acc8(acc, q0, n0); acc8(acc, q1, n1); acc8(acc, q2, n2); acc8(acc, q3, n3);
    }
    for (; e < end; e++) {
        int s0 = __ldg(adj + e);
        float n0 = __ldg(dinv + s0) * dd;
        uint4 q0 = *(const uint4*)(g + (size_t)s0 * OUTF + fo);
        acc8(acc, q0, n0);
    }

    float d2 = dd * dd;
    uint4 qs = *(const uint4*)(g + (size_t)node * OUTF + fo);
    float sf[8]; bq8(qs, sf);
    float4 bv0 = *(const float4*)(b2 + fo);
    float4 bv1 = *(const float4*)(b2 + fo + 4);
    float bb[8] = {bv0.x, bv0.y, bv0.z, bv0.w, bv1.x, bv1.y, bv1.z, bv1.w};
    float v[8];
    #pragma unroll
    for (int i = 0; i < 8; i++) v[i] = fmaf(d2, sf[i], acc[i]) + bb[i];

    float m = v[0];
    #pragma unroll
    for (int i = 1; i < 8; i++) m = fmaxf(m, v[i]);
    #pragma unroll
    for (int o = 4; o > 0; o >>= 1) m = fmaxf(m, __shfl_xor_sync(~0u, m, o, 8));
    float s = 0.f;
    #pragma unroll
    for (int i = 0; i < 8; i++) s += expf(v[i] - m);
    #pragma unroll
    for (int o = 4; o > 0; o >>= 1) s += __shfl_xor_sync(~0u, s, o, 8);
    float ls = m + logf(s);

    float* op = out + (size_t)node * OUTF + fo;
    *(float4*)(op)     = make_float4(v[0]-ls, v[1]-ls, v[2]-ls, v[3]-ls);
    *(float4*)(op + 4) = make_float4(v[4]-ls, v[5]-ls, v[6]-ls, v[7]-ls);
}

// ================= launch =======================================================
extern "C" void kernel_launch(void* const* d_in, const int* in_sizes, int n_in,
                              void* d_out, int out_size)
{
    const float* x  = (const float*)d_in[0];
    const int*   ei = (const int*)  d_in[1];
    // d_in[2] edge_weight: unused (CRF softmax over singleton groups == 1.0)
    const float* W1 = (const float*)d_in[3];
    const float* b1 = (const float*)d_in[4];
    const float* W2 = (const float*)d_in[5];
    const float* b2 = (const float*)d_in[6];
    float* out = (float*)d_out;

    const int n = in_sizes[0] / INF;
    const int E = in_sizes[2];
    const int* src = ei;
    const int* dst = ei + E;

    __nv_bfloat16 *h, *h2, *g, *w2hi, *w2lo;
    float *dinv, *w1t;
    int *cnt, *rowptr, *cursor, *adj, *bsum, *boff;
    cudaGetSymbolAddress((void**)&h,     g_h);
    cudaGetSymbolAddress((void**)&h2,    g_h2);
    cudaGetSymbolAddress((void**)&g,     g_g);
    cudaGetSymbolAddress((void**)&dinv,  g_dinv);
    cudaGetSymbolAddress((void**)&cnt,   g_cnt);
    cudaGetSymbolAddress((void**)&rowptr,g_rowptr);
    cudaGetSymbolAddress((void**)&cursor,g_cursor);
    cudaGetSymbolAddress((void**)&adj,   g_adj);
    cudaGetSymbolAddress((void**)&bsum,  g_bsum);
    cudaGetSymbolAddress((void**)&boff,  g_boff);
    cudaGetSymbolAddress((void**)&w1t,   g_w1t);
    cudaGetSymbolAddress((void**)&w2hi,  g_w2hi);
    cudaGetSymbolAddress((void**)&w2lo,  g_w2lo);

    const int nb = (n + SCAN_BS - 1) / SCAN_BS;
    const int mtiles = (n + 127) / 128;

    constexpr int SMEM1 = INF * HIDF * 4 + 2 * 32768 + 1024;
    constexpr int SMEM2 = 2 * (HIDF * OUTF * 2) + 2 * 16384 + 1024;
    cudaFuncSetAttribute(tf32_gemm, cudaFuncAttributeMaxDynamicSharedMemorySize, SMEM1);
    cudaFuncSetAttribute(bf16_gemm, cudaFuncAttributeMaxDynamicSharedMemorySize, SMEM2);

    static cudaStream_t sCsr = nullptr;
    static cudaEvent_t evFork = nullptr, evJoin = nullptr;
    if (!sCsr) {
        cudaStreamCreateWithFlags(&sCsr, cudaStreamNonBlocking);
        cudaEventCreateWithFlags(&evFork, cudaEventDisableTiming);
        cudaEventCreateWithFlags(&evJoin, cudaEventDisableTiming);
    }

    cudaEventRecord(evFork, 0);
    cudaStreamWaitEvent(sCsr, evFork, 0);

    // submission order puts tf32_gemm at launch slot 5 for ncu (-s 5):
    cudaMemsetAsync(cnt, 0, (size_t)n * sizeof(int), sCsr);                     // 1
    count_kernel<<<(E + 255)/256, 256, 0, sCsr>>>(dst, E, cnt);                 // 2
    scanA_kernel<<<nb, SCAN_BS, 0, sCsr>>>(cnt, n, bsum);                       // 3
    wtf32_kernel<<<(INF*HIDF + 255)/256, 256>>>(W1, INF, HIDF, w1t);            // 4
    tf32_gemm<<<148, 512, SMEM1>>>(x, INF, w1t, h, n, mtiles);                  // 5
    scanB_kernel<<<1, 128, 0, sCsr>>>(bsum, nb, boff, rowptr, n, E);            // 6
    scanC_kernel<<<nb, SCAN_BS, 0, sCsr>>>(cnt, boff, n, rowptr, cursor, dinv); // 7
    fill_kernel <<<(E + 255)/256, 256, 0, sCsr>>>(src, dst, E, cursor, adj);    // 8
    wsplit_kernel<<<(HIDF*OUTF + 255)/256, 256, 0, sCsr>>>(W2, HIDF, OUTF, w2hi, w2lo);
    cudaEventRecord(evJoin, sCsr);
    cudaStreamWaitEvent(0, evJoin, 0);

    agg1_kernel<<<((long long)n*16 + 255)/256, 256>>>(h, rowptr, adj, dinv, b1, h2, n);
    bf16_gemm<<<296, 256, SMEM2>>>(h2, HIDF, w2hi, w2lo, g, n, mtiles);
    agg2_kernel<<<((long long)n*8 + 255)/256, 256>>>(g, rowptr, adj, dinv, b2, out, n);
}